// round 1
// baseline (speedup 1.0000x reference)
#include <cuda_runtime.h>
#include <math.h>

#define NB    4096
#define SEQL  168
#define CF    64
#define NP    96
#define KW    25
#define PI_F  3.14159265358979f

// scratch (static device allocations; no cudaMalloc allowed)
__device__ float d_xT[(size_t)CF * SEQL * NB];      // [c][l][b]  176 MB
__device__ float d_MT[(size_t)CF * SEQL * 192];     // [c][l][2p interleaved] 8.25 MB
__device__ float d_mod[(size_t)NB * NP];            // [b][p]
__device__ float d_c12[2 * NP];                     // c1[p], c2[p]

// ---------------------------------------------------------------------------
// Kernel 0: transpose x[b][l][c] -> xT[c][l][b]  (coalesced both sides)
// ---------------------------------------------------------------------------
__global__ __launch_bounds__(256) void transpose_k(const float* __restrict__ x) {
    __shared__ float sh[32][65];
    const int l  = blockIdx.y;
    const int b0 = blockIdx.x * 32;
    const int tid = threadIdx.x;
    const float4* x4 = (const float4*)x;
    for (int i = tid; i < 512; i += 256) {
        int bb = i >> 4, c4 = i & 15;
        float4 v = x4[(size_t)(b0 + bb) * (SEQL * 16) + (size_t)l * 16 + c4];
        sh[bb][c4 * 4 + 0] = v.x; sh[bb][c4 * 4 + 1] = v.y;
        sh[bb][c4 * 4 + 2] = v.z; sh[bb][c4 * 4 + 3] = v.w;
    }
    __syncthreads();
    float4* xT4 = (float4*)d_xT;
    for (int i = tid; i < 512; i += 256) {
        int c = i >> 3, b4 = i & 7;
        float4 w;
        w.x = sh[b4 * 4 + 0][c]; w.y = sh[b4 * 4 + 1][c];
        w.z = sh[b4 * 4 + 2][c]; w.w = sh[b4 * 4 + 3][c];
        xT4[(size_t)(c * SEQL + l) * (NB / 4) + (b0 >> 2) + b4] = w;
    }
}

// ---------------------------------------------------------------------------
// Kernel 1: per-batch quantum path -> d_mod[b][p]
// ---------------------------------------------------------------------------
__device__ __forceinline__ float2 cmulf(float2 a, float2 b) {
    return make_float2(a.x * b.x - a.y * b.y, a.x * b.y + a.y * b.x);
}

__device__ void run_circuit(const float qin[4], const float* __restrict__ w, float2 s[16]) {
#pragma unroll
    for (int i = 0; i < 16; i++) s[i] = make_float2(0.f, 0.f);
    s[0].x = 1.f;
#pragma unroll
    for (int l = 0; l < 3; l++) {
        // RY(inputs) on each qubit
#pragma unroll
        for (int q = 0; q < 4; q++) {
            const int m = 8 >> q;
            float sn, cs; sincosf(0.5f * qin[q], &sn, &cs);
#pragma unroll
            for (int i = 0; i < 16; i++) {
                if ((i & m) == 0) {
                    float2 a0 = s[i], a1 = s[i | m];
                    s[i]     = make_float2(cs * a0.x - sn * a1.x, cs * a0.y - sn * a1.y);
                    s[i | m] = make_float2(sn * a0.x + cs * a1.x, sn * a0.y + cs * a1.y);
                }
            }
        }
        // Rot(phi, theta, omega) per qubit
#pragma unroll
        for (int q = 0; q < 4; q++) {
            const int m = 8 >> q;
            float phi = w[(l * 4 + q) * 3 + 0];
            float th  = w[(l * 4 + q) * 3 + 1];
            float om  = w[(l * 4 + q) * 3 + 2];
            float st, ct; sincosf(0.5f * th, &st, &ct);
            float s1, c1; sincosf(-0.5f * (phi + om), &s1, &c1);   // ep
            float s2, c2; sincosf( 0.5f * (phi - om), &s2, &c2);   // em
            float2 U00 = make_float2( c1 * ct,  s1 * ct);
            float2 U01 = make_float2(-c2 * st, -s2 * st);
            float2 U10 = make_float2( c2 * st, -s2 * st);
            float2 U11 = make_float2( c1 * ct, -s1 * ct);
#pragma unroll
            for (int i = 0; i < 16; i++) {
                if ((i & m) == 0) {
                    float2 a0 = s[i], a1 = s[i | m];
                    float2 n0 = cmulf(U00, a0); float2 t = cmulf(U01, a1);
                    n0.x += t.x; n0.y += t.y;
                    float2 n1 = cmulf(U10, a0); t = cmulf(U11, a1);
                    n1.x += t.x; n1.y += t.y;
                    s[i] = n0; s[i | m] = n1;
                }
            }
        }
        // CNOT ring q -> (q+1)%4 (sequential)
#pragma unroll
        for (int q = 0; q < 4; q++) {
            const int cm = 8 >> q;
            const int tm = 8 >> ((q + 1) & 3);
#pragma unroll
            for (int i = 0; i < 16; i++) {
                if ((i & cm) && !(i & tm)) {
                    float2 t = s[i]; s[i] = s[i | tm]; s[i | tm] = t;
                }
            }
        }
    }
}

__device__ __forceinline__ void expvals(const float2 s[16], int pauli, float* o) {
#pragma unroll
    for (int q = 0; q < 4; q++) {
        const int m = 8 >> q;
        float acc = 0.f;
#pragma unroll
        for (int i = 0; i < 16; i++) {
            if ((i & m) == 0) {
                float2 a0 = s[i], a1 = s[i | m];
                if (pauli == 0)      acc += a0.x * a1.x + a0.y * a1.y;             // Re conj(a0)a1
                else if (pauli == 1) acc += a0.x * a1.y - a0.y * a1.x;             // Im
                else                 acc += a0.x * a0.x + a0.y * a0.y
                                          - a1.x * a1.x - a1.y * a1.y;             // Z
            }
        }
        o[q] = (pauli == 2) ? acc : 2.f * acc;
    }
}

__global__ void mod_k(const float* __restrict__ x,
                      const float* __restrict__ lagc_W, const float* __restrict__ lagc_b,
                      const float* __restrict__ wx, const float* __restrict__ wy,
                      const float* __restrict__ wz,
                      const float* __restrict__ W1, const float* __restrict__ b1,
                      const float* __restrict__ W2, const float* __restrict__ b2) {
    int b = blockIdx.x * blockDim.x + threadIdx.x;
    if (b >= NB) return;
    const int lags[11] = {167, 166, 165, 164, 163, 162, 145, 144, 143, 1, 0};
    float lag[11];
#pragma unroll
    for (int j = 0; j < 11; j++)
        lag[j] = x[(size_t)b * (SEQL * CF) + lags[j] * CF + (CF - 1)];
    float qin[4];
#pragma unroll
    for (int q = 0; q < 4; q++) {
        float s = lagc_b[q];
#pragma unroll
        for (int j = 0; j < 11; j++) s += lag[j] * lagc_W[q * 11 + j];
        qin[q] = tanhf(s) * PI_F;
    }
    float feats[12];
    float2 st[16];
    run_circuit(qin, wx, st); expvals(st, 0, feats + 0);
    run_circuit(qin, wy, st); expvals(st, 1, feats + 4);
    run_circuit(qin, wz, st); expvals(st, 2, feats + 8);
    float h[12];
#pragma unroll
    for (int i = 0; i < 12; i++) {
        float s = b1[i];
#pragma unroll
        for (int j = 0; j < 12; j++) s += feats[j] * W1[i * 12 + j];
        h[i] = fmaxf(s, 0.f);
    }
    for (int p = 0; p < NP; p++) {
        float s = b2[p];
#pragma unroll
        for (int i = 0; i < 12; i++) s += h[i] * W2[p * 12 + i];
        d_mod[(size_t)b * NP + p] = tanhf(s);
    }
}

// ---------------------------------------------------------------------------
// Kernel 2: precompute combined per-channel matrices
//   M1 = a*(seas_W(I-Conv_c)) + (1-a)*trend_W*Conv_c ; M2 = a*(seas_W(I-Conv_c))
//   stored row-interleaved & l-major: d_MT[c][l][2p], d_MT[c][l][2p+1]
// ---------------------------------------------------------------------------
__global__ void prep_k(const float* __restrict__ decomp_w,
                       const float* __restrict__ trend_W, const float* __restrict__ trend_b,
                       const float* __restrict__ seas_W,  const float* __restrict__ seas_b,
                       const float* __restrict__ alpha) {
    const int c = blockIdx.x;   // 0..63
    const int p = blockIdx.y;   // 0..95
    const int j = threadIdx.x;  // 0..167 (source column index)
    __shared__ float ker[KW];
    __shared__ float a_sh;
    if (j == 0) {
        float mx = -1e30f;
        for (int k = 0; k < KW; k++) mx = fmaxf(mx, decomp_w[c * KW + k]);
        float sum = 0.f, e[KW];
        for (int k = 0; k < KW; k++) { e[k] = expf(decomp_w[c * KW + k] - mx); sum += e[k]; }
        for (int k = 0; k < KW; k++) ker[k] = e[k] / sum;
        a_sh = 1.f / (1.f + expf(-alpha[0]));
    }
    __syncthreads();
    const float a = a_sh;
    const float* sW = seas_W + p * SEQL;
    const float* tW = trend_W + p * SEQL;
    float sA = 0.f, sB = 0.f;   // (seas_W @ Conv)[p,j], (trend_W @ Conv)[p,j]
    if (j == 0) {
        for (int k = 0; k <= 12; k++) {
            float wk = ker[k];
            for (int l = 0; l <= 12 - k; l++) { sA += wk * sW[l]; sB += wk * tW[l]; }
        }
    } else if (j == SEQL - 1) {
        for (int k = 12; k < KW; k++) {
            float wk = ker[k];
            for (int l = 179 - k; l < SEQL; l++) { sA += wk * sW[l]; sB += wk * tW[l]; }
        }
    } else {
        for (int k = 0; k < KW; k++) {
            int l = j + 12 - k;
            if (l >= 0 && l < SEQL) { float wk = ker[k]; sA += wk * sW[l]; sB += wk * tW[l]; }
        }
    }
    float A  = sW[j] - sA;              // seas_W(I - Conv)
    float M1 = a * A + (1.f - a) * sB;
    float M2 = a * A;
    d_MT[(size_t)(c * SEQL + j) * 192 + 2 * p]     = M1;
    d_MT[(size_t)(c * SEQL + j) * 192 + 2 * p + 1] = M2;
    if (c == 0 && j == 0) {
        d_c12[p]      = a * seas_b[p] + (1.f - a) * trend_b[p];
        d_c12[NP + p] = a * seas_b[p];
    }
}

// ---------------------------------------------------------------------------
// Kernel 3: main batched GEMM + fused epilogue.
//   Per block: one channel c, a 64-batch tile, all 192 rows.
//   Thread tile: 12 rows x 4 batches (acc 48).
// ---------------------------------------------------------------------------
__global__ __launch_bounds__(256) void gemm_k(float* __restrict__ out) {
    const int c  = blockIdx.x;        // channels fastest -> L2 write merging on out
    const int b0 = blockIdx.y * 64;
    __shared__ float As[24 * 192];    // [k][r]  18 KB
    __shared__ float Bs[24 * 64];     // [k][b]   6 KB
    const int tid = threadIdx.x;
    const int tx = tid & 15;          // batch groups of 4
    const int ty = tid >> 4;          // row groups of 12

    float acc[12][4];
#pragma unroll
    for (int r = 0; r < 12; r++)
#pragma unroll
        for (int bb = 0; bb < 4; bb++) acc[r][bb] = 0.f;

    const float4* MT4 = (const float4*)d_MT;
    const float4* xT4 = (const float4*)d_xT;
    float4* As4 = (float4*)As;
    float4* Bs4 = (float4*)Bs;

    for (int kc = 0; kc < 7; kc++) {
        const int l0 = kc * 24;
        // A tile: 24 rows x 48 float4 (contiguous, no transpose needed)
#pragma unroll
        for (int i = tid; i < 24 * 48; i += 256) {
            int row = i / 48, r4 = i % 48;
            As4[row * 48 + r4] = MT4[(size_t)(c * SEQL + l0 + row) * 48 + r4];
        }
        // B tile: 24 rows x 16 float4
#pragma unroll
        for (int i = tid; i < 24 * 16; i += 256) {
            int row = i >> 4, b4 = i & 15;
            Bs4[row * 16 + b4] = xT4[(size_t)(c * SEQL + l0 + row) * (NB / 4) + (b0 >> 2) + b4];
        }
        __syncthreads();
#pragma unroll
        for (int k = 0; k < 24; k++) {
            float4 bq = Bs4[k * 16 + tx];
            float bv[4] = {bq.x, bq.y, bq.z, bq.w};
            float4 a0 = As4[k * 48 + ty * 3 + 0];
            float4 a1 = As4[k * 48 + ty * 3 + 1];
            float4 a2 = As4[k * 48 + ty * 3 + 2];
            float av[12] = {a0.x, a0.y, a0.z, a0.w,
                            a1.x, a1.y, a1.z, a1.w,
                            a2.x, a2.y, a2.z, a2.w};
#pragma unroll
            for (int r = 0; r < 12; r++)
#pragma unroll
                for (int bb = 0; bb < 4; bb++)
                    acc[r][bb] += av[r] * bv[bb];
        }
        __syncthreads();
    }

    // epilogue: rows 2i -> y1(p), 2i+1 -> y2(p), p = ty*6 + i
#pragma unroll
    for (int i = 0; i < 6; i++) {
        const int p = ty * 6 + i;
        const float C1 = d_c12[p];
        const float C2 = d_c12[NP + p];
#pragma unroll
        for (int bb = 0; bb < 4; bb++) {
            const int b = b0 + tx * 4 + bb;
            const float m = d_mod[(size_t)b * NP + p];
            out[(size_t)b * (NP * CF) + p * CF + c] =
                acc[2 * i][bb] + C1 + m * (acc[2 * i + 1][bb] + C2);
        }
    }
}

// ---------------------------------------------------------------------------
extern "C" void kernel_launch(void* const* d_in, const int* in_sizes, int n_in,
                              void* d_out, int out_size) {
    const float* x        = (const float*)d_in[0];
    const float* decomp_w = (const float*)d_in[1];
    const float* trend_W  = (const float*)d_in[2];
    const float* trend_b  = (const float*)d_in[3];
    const float* seas_W   = (const float*)d_in[4];
    const float* seas_b   = (const float*)d_in[5];
    const float* lagc_W   = (const float*)d_in[6];
    const float* lagc_b   = (const float*)d_in[7];
    const float* wx       = (const float*)d_in[8];
    const float* wy       = (const float*)d_in[9];
    const float* wz       = (const float*)d_in[10];
    const float* W1       = (const float*)d_in[11];
    const float* b1       = (const float*)d_in[12];
    const float* W2       = (const float*)d_in[13];
    const float* b2       = (const float*)d_in[14];
    const float* alpha    = (const float*)d_in[15];
    float* out = (float*)d_out;

    transpose_k<<<dim3(128, 168), 256>>>(x);
    mod_k<<<32, 128>>>(x, lagc_W, lagc_b, wx, wy, wz, W1, b1, W2, b2);
    prep_k<<<dim3(64, 96), 168>>>(decomp_w, trend_W, trend_b, seas_W, seas_b, alpha);
    gemm_k<<<dim3(64, 64), 256>>>(out);
}

// round 3
// speedup vs baseline: 1.3476x; 1.3476x over previous
#include <cuda_runtime.h>
#include <math.h>
#include <stdint.h>

#define NB    4096
#define SEQL  168
#define CF    64
#define NP    96
#define KW    25
#define PI_F  3.14159265358979f

// scratch
__device__ float d_xT[(size_t)CF * NB * SEQL];      // [c][b][k]  tf32-rounded (176MB)
__device__ float d_MT[(size_t)CF * 192 * SEQL];     // [c][n=2p interleaved][k] tf32 (8.25MB)
__device__ float d_mod[(size_t)NB * NP];
__device__ float d_c12[2 * NP];

__device__ __forceinline__ float to_tf32(float f) {
    uint32_t u;
    asm("cvt.rna.tf32.f32 %0, %1;" : "=r"(u) : "f"(f));
    return __uint_as_float(u);
}
__device__ __forceinline__ uint32_t smem_u32(const void* p) {
    uint32_t a;
    asm("{ .reg .u64 t; cvta.to.shared.u64 t, %1; cvt.u32.u64 %0, t; }" : "=r"(a) : "l"(p));
    return a;
}
__device__ __forceinline__ void cp16(uint32_t dst, const void* src) {
    asm volatile("cp.async.cg.shared.global [%0], [%1], 16;" :: "r"(dst), "l"(src));
}
__device__ __forceinline__ void mma_tf32(float* d, const uint32_t* a, const uint32_t* b) {
    asm volatile(
        "mma.sync.aligned.m16n8k8.row.col.f32.tf32.tf32.f32 "
        "{%0,%1,%2,%3}, {%4,%5,%6,%7}, {%8,%9}, {%0,%1,%2,%3};"
        : "+f"(d[0]), "+f"(d[1]), "+f"(d[2]), "+f"(d[3])
        : "r"(a[0]), "r"(a[1]), "r"(a[2]), "r"(a[3]), "r"(b[0]), "r"(b[1]));
}

// ---------------------------------------------------------------------------
// Kernel 0: transpose x[b][l][c] -> d_xT[c][b][k] (tf32-rounded)
// ---------------------------------------------------------------------------
__global__ __launch_bounds__(256) void transpose_k(const float* __restrict__ x) {
    __shared__ float sh[8][32][33];
    const int c0 = blockIdx.x * 8;
    const int l0 = blockIdx.y * 32;
    const int b0 = blockIdx.z * 32;
    const int tid = threadIdx.x;
    const float4* x4 = (const float4*)x;
#pragma unroll
    for (int it = 0; it < 8; it++) {
        int i = it * 256 + tid;
        int c4i = i & 1, l = (i >> 1) & 31, b = i >> 6;
        int lg = l0 + l;
        float4 v = make_float4(0.f, 0.f, 0.f, 0.f);
        if (lg < SEQL)
            v = x4[(size_t)(b0 + b) * (SEQL * 16) + (size_t)lg * 16 + (c0 >> 2) + c4i];
        sh[c4i * 4 + 0][l][b] = to_tf32(v.x);
        sh[c4i * 4 + 1][l][b] = to_tf32(v.y);
        sh[c4i * 4 + 2][l][b] = to_tf32(v.z);
        sh[c4i * 4 + 3][l][b] = to_tf32(v.w);
    }
    __syncthreads();
    float4* o4 = (float4*)d_xT;
#pragma unroll
    for (int it = 0; it < 8; it++) {
        int i = it * 256 + tid;
        int k4 = i & 7, b = (i >> 3) & 31, cl = i >> 8;
        if (l0 + k4 * 4 >= SEQL) continue;
        float4 w;
        w.x = sh[cl][k4 * 4 + 0][b];
        w.y = sh[cl][k4 * 4 + 1][b];
        w.z = sh[cl][k4 * 4 + 2][b];
        w.w = sh[cl][k4 * 4 + 3][b];
        o4[((size_t)(c0 + cl) * NB + b0 + b) * (SEQL / 4) + (l0 >> 2) + k4] = w;
    }
}

// ---------------------------------------------------------------------------
// Kernel 1: per-batch quantum path -> d_mod[b][p]
// ---------------------------------------------------------------------------
__device__ __forceinline__ float2 cmulf(float2 a, float2 b) {
    return make_float2(a.x * b.x - a.y * b.y, a.x * b.y + a.y * b.x);
}

__device__ void run_circuit(const float qin[4], const float* __restrict__ w, float2 s[16]) {
#pragma unroll
    for (int i = 0; i < 16; i++) s[i] = make_float2(0.f, 0.f);
    s[0].x = 1.f;
#pragma unroll
    for (int l = 0; l < 3; l++) {
#pragma unroll
        for (int q = 0; q < 4; q++) {
            const int m = 8 >> q;
            float sn, cs; sincosf(0.5f * qin[q], &sn, &cs);
#pragma unroll
            for (int i = 0; i < 16; i++) {
                if ((i & m) == 0) {
                    float2 a0 = s[i], a1 = s[i | m];
                    s[i]     = make_float2(cs * a0.x - sn * a1.x, cs * a0.y - sn * a1.y);
                    s[i | m] = make_float2(sn * a0.x + cs * a1.x, sn * a0.y + cs * a1.y);
                }
            }
        }
#pragma unroll
        for (int q = 0; q < 4; q++) {
            const int m = 8 >> q;
            float phi = w[(l * 4 + q) * 3 + 0];
            float th  = w[(l * 4 + q) * 3 + 1];
            float om  = w[(l * 4 + q) * 3 + 2];
            float st, ct; sincosf(0.5f * th, &st, &ct);
            float s1, c1; sincosf(-0.5f * (phi + om), &s1, &c1);
            float s2, c2; sincosf( 0.5f * (phi - om), &s2, &c2);
            float2 U00 = make_float2( c1 * ct,  s1 * ct);
            float2 U01 = make_float2(-c2 * st, -s2 * st);
            float2 U10 = make_float2( c2 * st, -s2 * st);
            float2 U11 = make_float2( c1 * ct, -s1 * ct);
#pragma unroll
            for (int i = 0; i < 16; i++) {
                if ((i & m) == 0) {
                    float2 a0 = s[i], a1 = s[i | m];
                    float2 n0 = cmulf(U00, a0); float2 t = cmulf(U01, a1);
                    n0.x += t.x; n0.y += t.y;
                    float2 n1 = cmulf(U10, a0); t = cmulf(U11, a1);
                    n1.x += t.x; n1.y += t.y;
                    s[i] = n0; s[i | m] = n1;
                }
            }
        }
#pragma unroll
        for (int q = 0; q < 4; q++) {
            const int cm = 8 >> q;
            const int tm = 8 >> ((q + 1) & 3);
#pragma unroll
            for (int i = 0; i < 16; i++) {
                if ((i & cm) && !(i & tm)) {
                    float2 t = s[i]; s[i] = s[i | tm]; s[i | tm] = t;
                }
            }
        }
    }
}

__device__ __forceinline__ void expvals(const float2 s[16], int pauli, float* o) {
#pragma unroll
    for (int q = 0; q < 4; q++) {
        const int m = 8 >> q;
        float acc = 0.f;
#pragma unroll
        for (int i = 0; i < 16; i++) {
            if ((i & m) == 0) {
                float2 a0 = s[i], a1 = s[i | m];
                if (pauli == 0)      acc += a0.x * a1.x + a0.y * a1.y;
                else if (pauli == 1) acc += a0.x * a1.y - a0.y * a1.x;
                else                 acc += a0.x * a0.x + a0.y * a0.y
                                          - a1.x * a1.x - a1.y * a1.y;
            }
        }
        o[q] = (pauli == 2) ? acc : 2.f * acc;
    }
}

__global__ __launch_bounds__(96) void mod_k(const float* __restrict__ x,
                      const float* __restrict__ lagc_W, const float* __restrict__ lagc_b,
                      const float* __restrict__ wx, const float* __restrict__ wy,
                      const float* __restrict__ wz,
                      const float* __restrict__ W1, const float* __restrict__ b1,
                      const float* __restrict__ W2, const float* __restrict__ b2) {
    __shared__ float feats_s[32][13];
    const int bl = threadIdx.x & 31;
    const int r  = threadIdx.x >> 5;
    const int b  = blockIdx.x * 32 + bl;
    const int lags[11] = {167, 166, 165, 164, 163, 162, 145, 144, 143, 1, 0};
    float lag[11];
#pragma unroll
    for (int j = 0; j < 11; j++)
        lag[j] = x[(size_t)b * (SEQL * CF) + lags[j] * CF + (CF - 1)];
    float qin[4];
#pragma unroll
    for (int q = 0; q < 4; q++) {
        float s = lagc_b[q];
#pragma unroll
        for (int j = 0; j < 11; j++) s += lag[j] * lagc_W[q * 11 + j];
        qin[q] = tanhf(s) * PI_F;
    }
    const float* w = (r == 0) ? wx : (r == 1) ? wy : wz;
    float2 st[16];
    float f4[4];
    run_circuit(qin, w, st);
    expvals(st, r, f4);
#pragma unroll
    for (int q = 0; q < 4; q++) feats_s[bl][r * 4 + q] = f4[q];
    __syncthreads();
    float feats[12];
#pragma unroll
    for (int j = 0; j < 12; j++) feats[j] = feats_s[bl][j];
    float h[12];
#pragma unroll
    for (int i = 0; i < 12; i++) {
        float s = b1[i];
#pragma unroll
        for (int j = 0; j < 12; j++) s += feats[j] * W1[i * 12 + j];
        h[i] = fmaxf(s, 0.f);
    }
    for (int pp = 0; pp < 32; pp++) {
        int p = r * 32 + pp;
        float s = b2[p];
#pragma unroll
        for (int i = 0; i < 12; i++) s += h[i] * W2[p * 12 + i];
        d_mod[(size_t)b * NP + p] = tanhf(s);
    }
}

// ---------------------------------------------------------------------------
// Kernel 2: combined matrices -> d_MT[c][n=2p|2p+1][k] tf32-rounded
// ---------------------------------------------------------------------------
__global__ void prep_k(const float* __restrict__ decomp_w,
                       const float* __restrict__ trend_W, const float* __restrict__ trend_b,
                       const float* __restrict__ seas_W,  const float* __restrict__ seas_b,
                       const float* __restrict__ alpha) {
    const int c = blockIdx.x;
    const int p = blockIdx.y;
    const int j = threadIdx.x;  // 0..167
    __shared__ float ker[KW];
    __shared__ float a_sh;
    if (j == 0) {
        float mx = -1e30f;
        for (int k = 0; k < KW; k++) mx = fmaxf(mx, decomp_w[c * KW + k]);
        float sum = 0.f, e[KW];
        for (int k = 0; k < KW; k++) { e[k] = expf(decomp_w[c * KW + k] - mx); sum += e[k]; }
        for (int k = 0; k < KW; k++) ker[k] = e[k] / sum;
        a_sh = 1.f / (1.f + expf(-alpha[0]));
    }
    __syncthreads();
    const float a = a_sh;
    const float* sW = seas_W + p * SEQL;
    const float* tW = trend_W + p * SEQL;
    float sA = 0.f, sB = 0.f;
    if (j == 0) {
        for (int k = 0; k <= 12; k++) {
            float wk = ker[k];
            for (int l = 0; l <= 12 - k; l++) { sA += wk * sW[l]; sB += wk * tW[l]; }
        }
    } else if (j == SEQL - 1) {
        for (int k = 12; k < KW; k++) {
            float wk = ker[k];
            for (int l = 179 - k; l < SEQL; l++) { sA += wk * sW[l]; sB += wk * tW[l]; }
        }
    } else {
        for (int k = 0; k < KW; k++) {
            int l = j + 12 - k;
            if (l >= 0 && l < SEQL) { float wk = ker[k]; sA += wk * sW[l]; sB += wk * tW[l]; }
        }
    }
    float A = sW[j] - sA;
    d_MT[((size_t)c * 192 + 2 * p)     * SEQL + j] = to_tf32(a * A + (1.f - a) * sB);
    d_MT[((size_t)c * 192 + 2 * p + 1) * SEQL + j] = to_tf32(a * A);
    if (c == 0 && j == 0) {
        d_c12[p]      = a * seas_b[p] + (1.f - a) * trend_b[p];
        d_c12[NP + p] = a * seas_b[p];
    }
}

// ---------------------------------------------------------------------------
// Kernel 3: TF32 mma.sync GEMM. Per CTA: channel c, 128 batches (M), 192 rows (N).
// K=168 in 7 chunks of 24. smem stride 28 floats (bank-conflict-free frag LDS).
// Warp tile: m=64 (4x m16), n=48 (6x n8). 8 warps = 2m x 4n.
// ---------------------------------------------------------------------------
#define KC        24
#define AS_STRIDE 28
#define AS_WORDS  (128 * AS_STRIDE)              // 3584
#define BS_WORDS  (192 * AS_STRIDE)              // 5376
#define STAGE_W   (AS_WORDS + BS_WORDS)          // 8960 words = 35840 B

__global__ __launch_bounds__(256) void gemm_k(float* __restrict__ out) {
    extern __shared__ __align__(16) float sm[];
    const int c   = blockIdx.x;                  // c fastest -> L2 write merging
    const int b0  = blockIdx.y * 128;
    const int tid = threadIdx.x;
    const int wid  = tid >> 5;
    const int lane = tid & 31;
    const int gid  = lane >> 2;
    const int tig  = lane & 3;
    const int warp_m = (wid & 1) * 64;
    const int warp_n = (wid >> 1) * 48;

    const float* Ag = d_xT + ((size_t)c * NB + b0) * SEQL;
    const float* Bg = d_MT + (size_t)c * 192 * SEQL;
    const uint32_t smb = smem_u32(sm);

    auto load_stage = [&](int s, int kc) {
        const uint32_t A0 = smb + s * (STAGE_W * 4);
        const uint32_t B0 = A0 + AS_WORDS * 4;
        {   // A: 128 rows, 2 threads/row, 3x16B each
            int row = tid >> 1, half = tid & 1;
            const float* src = Ag + (size_t)row * SEQL + kc * KC + half * 12;
            uint32_t dst = A0 + row * (AS_STRIDE * 4) + half * 48;
#pragma unroll
            for (int j = 0; j < 3; j++) cp16(dst + j * 16, src + j * 4);
        }
        // B: 192 rows, 2 threads/row
#pragma unroll
        for (int i = tid; i < 384; i += 256) {
            int row = i >> 1, half = i & 1;
            const float* src = Bg + (size_t)row * SEQL + kc * KC + half * 12;
            uint32_t dst = B0 + row * (AS_STRIDE * 4) + half * 48;
#pragma unroll
            for (int j = 0; j < 3; j++) cp16(dst + j * 16, src + j * 4);
        }
    };

    float acc[4][6][4];
#pragma unroll
    for (int mi = 0; mi < 4; mi++)
#pragma unroll
        for (int ni = 0; ni < 6; ni++)
#pragma unroll
            for (int r = 0; r < 4; r++) acc[mi][ni][r] = 0.f;

    load_stage(0, 0);
    asm volatile("cp.async.commit_group;" ::: "memory");
    load_stage(1, 1);
    asm volatile("cp.async.commit_group;" ::: "memory");

    for (int kc = 0; kc < 7; kc++) {
        const int s = kc & 1;
        asm volatile("cp.async.wait_group 1;" ::: "memory");
        __syncthreads();
        const float* As = sm + s * STAGE_W;
        const float* Bs = As + AS_WORDS;
#pragma unroll
        for (int ks = 0; ks < 3; ks++) {
            const int k0 = ks * 8;
            uint32_t af[4][4], bf[6][2];
#pragma unroll
            for (int mi = 0; mi < 4; mi++) {
                const float* ap = As + (warp_m + mi * 16 + gid) * AS_STRIDE + k0 + tig;
                af[mi][0] = __float_as_uint(ap[0]);
                af[mi][1] = __float_as_uint(ap[8 * AS_STRIDE]);
                af[mi][2] = __float_as_uint(ap[4]);
                af[mi][3] = __float_as_uint(ap[8 * AS_STRIDE + 4]);
            }
#pragma unroll
            for (int ni = 0; ni < 6; ni++) {
                const float* bp = Bs + (warp_n + ni * 8 + gid) * AS_STRIDE + k0 + tig;
                bf[ni][0] = __float_as_uint(bp[0]);
                bf[ni][1] = __float_as_uint(bp[4]);
            }
#pragma unroll
            for (int mi = 0; mi < 4; mi++)
#pragma unroll
                for (int ni = 0; ni < 6; ni++)
                    mma_tf32(acc[mi][ni], af[mi], bf[ni]);
        }
        __syncthreads();
        if (kc + 2 < 7) load_stage(s, kc + 2);
        asm volatile("cp.async.commit_group;" ::: "memory");
    }

    // epilogue: (c0,c1) = (y1,y2) for p = warp_n/2 + ni*4 + tig, b = b0+warp_m+mi*16+gid
    const int pbase = warp_n / 2;
#pragma unroll
    for (int ni = 0; ni < 6; ni++) {
        const int p = pbase + ni * 4 + tig;
        const float C1 = d_c12[p];
        const float C2 = d_c12[NP + p];
#pragma unroll
        for (int mi = 0; mi < 4; mi++) {
#pragma unroll
            for (int h = 0; h < 2; h++) {
                const int b = b0 + warp_m + mi * 16 + gid + h * 8;
                const float y1 = acc[mi][ni][2 * h];
                const float y2 = acc[mi][ni][2 * h + 1];
                const float m = d_mod[(size_t)b * NP + p];
                out[(size_t)b * (NP * CF) + (size_t)p * CF + c] =
                    y1 + C1 + m * (y2 + C2);
            }
        }
    }
}

// ---------------------------------------------------------------------------
extern "C" void kernel_launch(void* const* d_in, const int* in_sizes, int n_in,
                              void* d_out, int out_size) {
    const float* x        = (const float*)d_in[0];
    const float* decomp_w = (const float*)d_in[1];
    const float* trend_W  = (const float*)d_in[2];
    const float* trend_b  = (const float*)d_in[3];
    const float* seas_W   = (const float*)d_in[4];
    const float* seas_b   = (const float*)d_in[5];
    const float* lagc_W   = (const float*)d_in[6];
    const float* lagc_b   = (const float*)d_in[7];
    const float* wx       = (const float*)d_in[8];
    const float* wy       = (const float*)d_in[9];
    const float* wz       = (const float*)d_in[10];
    const float* W1       = (const float*)d_in[11];
    const float* b1       = (const float*)d_in[12];
    const float* W2       = (const float*)d_in[13];
    const float* b2       = (const float*)d_in[14];
    const float* alpha    = (const float*)d_in[15];
    float* out = (float*)d_out;

    cudaFuncSetAttribute(gemm_k, cudaFuncAttributeMaxDynamicSharedMemorySize,
                         2 * STAGE_W * 4);

    transpose_k<<<dim3(8, 6, 128), 256>>>(x);
    mod_k<<<128, 96>>>(x, lagc_W, lagc_b, wx, wy, wz, W1, b1, W2, b2);
    prep_k<<<dim3(64, 96), 168>>>(decomp_w, trend_W, trend_b, seas_W, seas_b, alpha);
    gemm_k<<<dim3(64, 32), 256, 2 * STAGE_W * 4>>>(out);
}

// round 4
// speedup vs baseline: 1.3675x; 1.0148x over previous
#include <cuda_runtime.h>
#include <math.h>
#include <stdint.h>

#define NB    4096
#define SEQL  168
#define CF    64
#define NP    96
#define KW    25
#define PI_F  3.14159265358979f

// scratch
__device__ float d_xT[(size_t)CF * NB * SEQL];      // [c][b][k]  tf32-rounded (176MB)
__device__ float d_MT[(size_t)CF * 192 * SEQL];     // [c][n=2p interleaved][k] tf32 (8.25MB)
__device__ float d_mod[(size_t)NB * NP];
__device__ float d_c12[2 * NP];

__device__ __forceinline__ float to_tf32(float f) {
    uint32_t u;
    asm("cvt.rna.tf32.f32 %0, %1;" : "=r"(u) : "f"(f));
    return __uint_as_float(u);
}
__device__ __forceinline__ uint32_t smem_u32(const void* p) {
    uint32_t a;
    asm("{ .reg .u64 t; cvta.to.shared.u64 t, %1; cvt.u32.u64 %0, t; }" : "=r"(a) : "l"(p));
    return a;
}
__device__ __forceinline__ void cp16(uint32_t dst, const void* src) {
    asm volatile("cp.async.cg.shared.global [%0], [%1], 16;" :: "r"(dst), "l"(src));
}
__device__ __forceinline__ void mma_tf32(float* d, const uint32_t* a, const uint32_t* b) {
    asm volatile(
        "mma.sync.aligned.m16n8k8.row.col.f32.tf32.tf32.f32 "
        "{%0,%1,%2,%3}, {%4,%5,%6,%7}, {%8,%9}, {%0,%1,%2,%3};"
        : "+f"(d[0]), "+f"(d[1]), "+f"(d[2]), "+f"(d[3])
        : "r"(a[0]), "r"(a[1]), "r"(a[2]), "r"(a[3]), "r"(b[0]), "r"(b[1]));
}

// ---------------------------------------------------------------------------
// Kernel 0: transpose x[b][l][c] -> d_xT[c][b][k] (tf32-rounded)
// ---------------------------------------------------------------------------
__global__ __launch_bounds__(256) void transpose_k(const float* __restrict__ x) {
    __shared__ float sh[8][32][33];
    const int c0 = blockIdx.x * 8;
    const int l0 = blockIdx.y * 32;
    const int b0 = blockIdx.z * 32;
    const int tid = threadIdx.x;
    const float4* x4 = (const float4*)x;
#pragma unroll
    for (int it = 0; it < 8; it++) {
        int i = it * 256 + tid;
        int c4i = i & 1, l = (i >> 1) & 31, b = i >> 6;
        int lg = l0 + l;
        float4 v = make_float4(0.f, 0.f, 0.f, 0.f);
        if (lg < SEQL)
            v = x4[(size_t)(b0 + b) * (SEQL * 16) + (size_t)lg * 16 + (c0 >> 2) + c4i];
        sh[c4i * 4 + 0][l][b] = to_tf32(v.x);
        sh[c4i * 4 + 1][l][b] = to_tf32(v.y);
        sh[c4i * 4 + 2][l][b] = to_tf32(v.z);
        sh[c4i * 4 + 3][l][b] = to_tf32(v.w);
    }
    __syncthreads();
    float4* o4 = (float4*)d_xT;
#pragma unroll
    for (int it = 0; it < 8; it++) {
        int i = it * 256 + tid;
        int k4 = i & 7, b = (i >> 3) & 31, cl = i >> 8;
        if (l0 + k4 * 4 >= SEQL) continue;
        float4 w;
        w.x = sh[cl][k4 * 4 + 0][b];
        w.y = sh[cl][k4 * 4 + 1][b];
        w.z = sh[cl][k4 * 4 + 2][b];
        w.w = sh[cl][k4 * 4 + 3][b];
        o4[((size_t)(c0 + cl) * NB + b0 + b) * (SEQL / 4) + (l0 >> 2) + k4] = w;
    }
}

// ---------------------------------------------------------------------------
// Kernel 1: per-batch quantum path -> d_mod[b][p]
// ---------------------------------------------------------------------------
__device__ __forceinline__ float2 cmulf(float2 a, float2 b) {
    return make_float2(a.x * b.x - a.y * b.y, a.x * b.y + a.y * b.x);
}

__device__ void run_circuit(const float qin[4], const float* __restrict__ w, float2 s[16]) {
#pragma unroll
    for (int i = 0; i < 16; i++) s[i] = make_float2(0.f, 0.f);
    s[0].x = 1.f;
#pragma unroll
    for (int l = 0; l < 3; l++) {
#pragma unroll
        for (int q = 0; q < 4; q++) {
            const int m = 8 >> q;
            float sn, cs; sincosf(0.5f * qin[q], &sn, &cs);
#pragma unroll
            for (int i = 0; i < 16; i++) {
                if ((i & m) == 0) {
                    float2 a0 = s[i], a1 = s[i | m];
                    s[i]     = make_float2(cs * a0.x - sn * a1.x, cs * a0.y - sn * a1.y);
                    s[i | m] = make_float2(sn * a0.x + cs * a1.x, sn * a0.y + cs * a1.y);
                }
            }
        }
#pragma unroll
        for (int q = 0; q < 4; q++) {
            const int m = 8 >> q;
            float phi = w[(l * 4 + q) * 3 + 0];
            float th  = w[(l * 4 + q) * 3 + 1];
            float om  = w[(l * 4 + q) * 3 + 2];
            float st, ct; sincosf(0.5f * th, &st, &ct);
            float s1, c1; sincosf(-0.5f * (phi + om), &s1, &c1);
            float s2, c2; sincosf( 0.5f * (phi - om), &s2, &c2);
            float2 U00 = make_float2( c1 * ct,  s1 * ct);
            float2 U01 = make_float2(-c2 * st, -s2 * st);
            float2 U10 = make_float2( c2 * st, -s2 * st);
            float2 U11 = make_float2( c1 * ct, -s1 * ct);
#pragma unroll
            for (int i = 0; i < 16; i++) {
                if ((i & m) == 0) {
                    float2 a0 = s[i], a1 = s[i | m];
                    float2 n0 = cmulf(U00, a0); float2 t = cmulf(U01, a1);
                    n0.x += t.x; n0.y += t.y;
                    float2 n1 = cmulf(U10, a0); t = cmulf(U11, a1);
                    n1.x += t.x; n1.y += t.y;
                    s[i] = n0; s[i | m] = n1;
                }
            }
        }
#pragma unroll
        for (int q = 0; q < 4; q++) {
            const int cm = 8 >> q;
            const int tm = 8 >> ((q + 1) & 3);
#pragma unroll
            for (int i = 0; i < 16; i++) {
                if ((i & cm) && !(i & tm)) {
                    float2 t = s[i]; s[i] = s[i | tm]; s[i | tm] = t;
                }
            }
        }
    }
}

__device__ __forceinline__ void expvals(const float2 s[16], int pauli, float* o) {
#pragma unroll
    for (int q = 0; q < 4; q++) {
        const int m = 8 >> q;
        float acc = 0.f;
#pragma unroll
        for (int i = 0; i < 16; i++) {
            if ((i & m) == 0) {
                float2 a0 = s[i], a1 = s[i | m];
                if (pauli == 0)      acc += a0.x * a1.x + a0.y * a1.y;
                else if (pauli == 1) acc += a0.x * a1.y - a0.y * a1.x;
                else                 acc += a0.x * a0.x + a0.y * a0.y
                                          - a1.x * a1.x - a1.y * a1.y;
            }
        }
        o[q] = (pauli == 2) ? acc : 2.f * acc;
    }
}

__global__ __launch_bounds__(96) void mod_k(const float* __restrict__ x,
                      const float* __restrict__ lagc_W, const float* __restrict__ lagc_b,
                      const float* __restrict__ wx, const float* __restrict__ wy,
                      const float* __restrict__ wz,
                      const float* __restrict__ W1, const float* __restrict__ b1,
                      const float* __restrict__ W2, const float* __restrict__ b2) {
    __shared__ float feats_s[32][13];
    const int bl = threadIdx.x & 31;
    const int r  = threadIdx.x >> 5;
    const int b  = blockIdx.x * 32 + bl;
    const int lags[11] = {167, 166, 165, 164, 163, 162, 145, 144, 143, 1, 0};
    float lag[11];
#pragma unroll
    for (int j = 0; j < 11; j++)
        lag[j] = x[(size_t)b * (SEQL * CF) + lags[j] * CF + (CF - 1)];
    float qin[4];
#pragma unroll
    for (int q = 0; q < 4; q++) {
        float s = lagc_b[q];
#pragma unroll
        for (int j = 0; j < 11; j++) s += lag[j] * lagc_W[q * 11 + j];
        qin[q] = tanhf(s) * PI_F;
    }
    const float* w = (r == 0) ? wx : (r == 1) ? wy : wz;
    float2 st[16];
    float f4[4];
    run_circuit(qin, w, st);
    expvals(st, r, f4);
#pragma unroll
    for (int q = 0; q < 4; q++) feats_s[bl][r * 4 + q] = f4[q];
    __syncthreads();
    float feats[12];
#pragma unroll
    for (int j = 0; j < 12; j++) feats[j] = feats_s[bl][j];
    float h[12];
#pragma unroll
    for (int i = 0; i < 12; i++) {
        float s = b1[i];
#pragma unroll
        for (int j = 0; j < 12; j++) s += feats[j] * W1[i * 12 + j];
        h[i] = fmaxf(s, 0.f);
    }
    for (int pp = 0; pp < 32; pp++) {
        int p = r * 32 + pp;
        float s = b2[p];
#pragma unroll
        for (int i = 0; i < 12; i++) s += h[i] * W2[p * 12 + i];
        d_mod[(size_t)b * NP + p] = tanhf(s);
    }
}

// ---------------------------------------------------------------------------
// Kernel 2: combined matrices -> d_MT[c][n=2p|2p+1][k] tf32-rounded
// ---------------------------------------------------------------------------
__global__ void prep_k(const float* __restrict__ decomp_w,
                       const float* __restrict__ trend_W, const float* __restrict__ trend_b,
                       const float* __restrict__ seas_W,  const float* __restrict__ seas_b,
                       const float* __restrict__ alpha) {
    const int c = blockIdx.x;
    const int p = blockIdx.y;
    const int j = threadIdx.x;  // 0..167
    __shared__ float ker[KW];
    __shared__ float a_sh;
    if (j == 0) {
        float mx = -1e30f;
        for (int k = 0; k < KW; k++) mx = fmaxf(mx, decomp_w[c * KW + k]);
        float sum = 0.f, e[KW];
        for (int k = 0; k < KW; k++) { e[k] = expf(decomp_w[c * KW + k] - mx); sum += e[k]; }
        for (int k = 0; k < KW; k++) ker[k] = e[k] / sum;
        a_sh = 1.f / (1.f + expf(-alpha[0]));
    }
    __syncthreads();
    const float a = a_sh;
    const float* sW = seas_W + p * SEQL;
    const float* tW = trend_W + p * SEQL;
    float sA = 0.f, sB = 0.f;
    if (j == 0) {
        for (int k = 0; k <= 12; k++) {
            float wk = ker[k];
            for (int l = 0; l <= 12 - k; l++) { sA += wk * sW[l]; sB += wk * tW[l]; }
        }
    } else if (j == SEQL - 1) {
        for (int k = 12; k < KW; k++) {
            float wk = ker[k];
            for (int l = 179 - k; l < SEQL; l++) { sA += wk * sW[l]; sB += wk * tW[l]; }
        }
    } else {
        for (int k = 0; k < KW; k++) {
            int l = j + 12 - k;
            if (l >= 0 && l < SEQL) { float wk = ker[k]; sA += wk * sW[l]; sB += wk * tW[l]; }
        }
    }
    float A = sW[j] - sA;
    d_MT[((size_t)c * 192 + 2 * p)     * SEQL + j] = to_tf32(a * A + (1.f - a) * sB);
    d_MT[((size_t)c * 192 + 2 * p + 1) * SEQL + j] = to_tf32(a * A);
    if (c == 0 && j == 0) {
        d_c12[p]      = a * seas_b[p] + (1.f - a) * trend_b[p];
        d_c12[NP + p] = a * seas_b[p];
    }
}

// ---------------------------------------------------------------------------
// Kernel 3: TF32 mma.sync GEMM. Per CTA: channel c, 128 batches (M), 192 rows (N).
// 512 threads, 16 warps as 4m x 4n, warp tile m32 x n48.
// K=168 in 7 chunks of 24, 3-stage cp.async pipeline, smem stride 28.
// ---------------------------------------------------------------------------
#define KC        24
#define AS_STRIDE 28
#define AS_WORDS  (128 * AS_STRIDE)              // 3584
#define BS_WORDS  (192 * AS_STRIDE)              // 5376
#define STAGE_W   (AS_WORDS + BS_WORDS)          // 8960 words = 35840 B
#define NSTAGE    3

__global__ __launch_bounds__(512) void gemm_k(float* __restrict__ out) {
    extern __shared__ __align__(16) float sm[];
    const int c   = blockIdx.x;                  // c fastest -> L2 write merging
    const int b0  = blockIdx.y * 128;
    const int tid = threadIdx.x;
    const int wid  = tid >> 5;
    const int lane = tid & 31;
    const int gid  = lane >> 2;
    const int tig  = lane & 3;
    const int warp_m = (wid & 3) * 32;
    const int warp_n = (wid >> 2) * 48;

    const float* Ag = d_xT + ((size_t)c * NB + b0) * SEQL;
    const float* Bg = d_MT + (size_t)c * 192 * SEQL;
    const uint32_t smb = smem_u32(sm);

    auto load_stage = [&](int s, int kc) {
        const uint32_t A0 = smb + s * (STAGE_W * 4);
        const uint32_t B0 = A0 + AS_WORDS * 4;
        if (tid < 256) {                 // A: 128 rows x 2 halves
            int row = tid >> 1, half = tid & 1;
            const float* src = Ag + (size_t)row * SEQL + kc * KC + half * 12;
            uint32_t dst = A0 + row * (AS_STRIDE * 4) + half * 48;
#pragma unroll
            for (int j = 0; j < 3; j++) cp16(dst + j * 16, src + j * 4);
        } else {                         // B rows 0..127
            int i = tid - 256;
            int row = i >> 1, half = i & 1;
            const float* src = Bg + (size_t)row * SEQL + kc * KC + half * 12;
            uint32_t dst = B0 + row * (AS_STRIDE * 4) + half * 48;
#pragma unroll
            for (int j = 0; j < 3; j++) cp16(dst + j * 16, src + j * 4);
        }
        if (tid < 128) {                 // B rows 128..191
            int i = tid + 256;
            int row = i >> 1, half = i & 1;
            const float* src = Bg + (size_t)row * SEQL + kc * KC + half * 12;
            uint32_t dst = B0 + row * (AS_STRIDE * 4) + half * 48;
#pragma unroll
            for (int j = 0; j < 3; j++) cp16(dst + j * 16, src + j * 4);
        }
    };

    float acc[2][6][4];
#pragma unroll
    for (int mi = 0; mi < 2; mi++)
#pragma unroll
        for (int ni = 0; ni < 6; ni++)
#pragma unroll
            for (int r = 0; r < 4; r++) acc[mi][ni][r] = 0.f;

    load_stage(0, 0);
    asm volatile("cp.async.commit_group;" ::: "memory");
    load_stage(1, 1);
    asm volatile("cp.async.commit_group;" ::: "memory");
    load_stage(2, 2);
    asm volatile("cp.async.commit_group;" ::: "memory");

    int s = 0;
    for (int kc = 0; kc < 7; kc++) {
        asm volatile("cp.async.wait_group 2;" ::: "memory");
        __syncthreads();
        const float* As = sm + s * STAGE_W;
        const float* Bs = As + AS_WORDS;
#pragma unroll
        for (int ks = 0; ks < 3; ks++) {
            const int k0 = ks * 8;
            uint32_t af[2][4], bf[6][2];
#pragma unroll
            for (int mi = 0; mi < 2; mi++) {
                const float* ap = As + (warp_m + mi * 16 + gid) * AS_STRIDE + k0 + tig;
                af[mi][0] = __float_as_uint(ap[0]);
                af[mi][1] = __float_as_uint(ap[8 * AS_STRIDE]);
                af[mi][2] = __float_as_uint(ap[4]);
                af[mi][3] = __float_as_uint(ap[8 * AS_STRIDE + 4]);
            }
#pragma unroll
            for (int ni = 0; ni < 6; ni++) {
                const float* bp = Bs + (warp_n + ni * 8 + gid) * AS_STRIDE + k0 + tig;
                bf[ni][0] = __float_as_uint(bp[0]);
                bf[ni][1] = __float_as_uint(bp[4]);
            }
#pragma unroll
            for (int mi = 0; mi < 2; mi++)
#pragma unroll
                for (int ni = 0; ni < 6; ni++)
                    mma_tf32(acc[mi][ni], af[mi], bf[ni]);
        }
        __syncthreads();
        if (kc + 3 < 7) load_stage(s, kc + 3);
        asm volatile("cp.async.commit_group;" ::: "memory");
        s = (s == NSTAGE - 1) ? 0 : s + 1;
    }

    // epilogue: (c0,c1) = (y1,y2); p = warp_n/2 + ni*4 + tig; b = b0+warp_m+mi*16+gid+h*8
    const int pbase = warp_n >> 1;
#pragma unroll
    for (int ni = 0; ni < 6; ni++) {
        const int p = pbase + ni * 4 + tig;
        const float C1 = d_c12[p];
        const float C2 = d_c12[NP + p];
#pragma unroll
        for (int mi = 0; mi < 2; mi++) {
#pragma unroll
            for (int h = 0; h < 2; h++) {
                const int b = b0 + warp_m + mi * 16 + gid + h * 8;
                const float y1 = acc[mi][ni][2 * h];
                const float y2 = acc[mi][ni][2 * h + 1];
                const float m = d_mod[(size_t)b * NP + p];
                out[(size_t)b * (NP * CF) + (size_t)p * CF + c] =
                    y1 + C1 + m * (y2 + C2);
            }
        }
    }
}

// ---------------------------------------------------------------------------
extern "C" void kernel_launch(void* const* d_in, const int* in_sizes, int n_in,
                              void* d_out, int out_size) {
    const float* x        = (const float*)d_in[0];
    const float* decomp_w = (const float*)d_in[1];
    const float* trend_W  = (const float*)d_in[2];
    const float* trend_b  = (const float*)d_in[3];
    const float* seas_W   = (const float*)d_in[4];
    const float* seas_b   = (const float*)d_in[5];
    const float* lagc_W   = (const float*)d_in[6];
    const float* lagc_b   = (const float*)d_in[7];
    const float* wx       = (const float*)d_in[8];
    const float* wy       = (const float*)d_in[9];
    const float* wz       = (const float*)d_in[10];
    const float* W1       = (const float*)d_in[11];
    const float* b1       = (const float*)d_in[12];
    const float* W2       = (const float*)d_in[13];
    const float* b2       = (const float*)d_in[14];
    const float* alpha    = (const float*)d_in[15];
    float* out = (float*)d_out;

    cudaFuncSetAttribute(gemm_k, cudaFuncAttributeMaxDynamicSharedMemorySize,
                         NSTAGE * STAGE_W * 4);

    transpose_k<<<dim3(8, 6, 128), 256>>>(x);
    mod_k<<<128, 96>>>(x, lagc_W, lagc_b, wx, wy, wz, W1, b1, W2, b2);
    prep_k<<<dim3(64, 96), 168>>>(decomp_w, trend_W, trend_b, seas_W, seas_b, alpha);
    gemm_k<<<dim3(64, 32), 512, NSTAGE * STAGE_W * 4>>>(out);
}

// round 5
// speedup vs baseline: 1.7055x; 1.2472x over previous
#include <cuda_runtime.h>
#include <math.h>
#include <stdint.h>

#define NB    4096
#define SEQL  168
#define CF    64
#define NP    96
#define KW    25
#define PI_F  3.14159265358979f

// fragment-order scratch:
// d_xT: [c][mb(256)][kb(21)][128]  (m16xk8 fragment blocks, lane*4+reg)
// d_MT: [c][np(12)][kb(21)][128]   (n16xk8 fragment blocks: 2 n8 blocks/pair)
__device__ float d_xT[(size_t)CF * 256 * 21 * 128];
__device__ float d_MT[(size_t)CF * 12 * 21 * 128];
__device__ float d_mod[(size_t)NB * NP];
__device__ float d_c12[2 * NP];

__device__ __forceinline__ float to_tf32(float f) {
    uint32_t u;
    asm("cvt.rna.tf32.f32 %0, %1;" : "=r"(u) : "f"(f));
    return __uint_as_float(u);
}
__device__ __forceinline__ uint32_t smem_u32(const void* p) {
    uint32_t a;
    asm("{ .reg .u64 t; cvta.to.shared.u64 t, %1; cvt.u32.u64 %0, t; }" : "=r"(a) : "l"(p));
    return a;
}
__device__ __forceinline__ void cp16(uint32_t dst, const void* src) {
    asm volatile("cp.async.cg.shared.global [%0], [%1], 16;" :: "r"(dst), "l"(src));
}
__device__ __forceinline__ void mma_tf32(float* d, const uint32_t* a, const uint32_t* b) {
    asm volatile(
        "mma.sync.aligned.m16n8k8.row.col.f32.tf32.tf32.f32 "
        "{%0,%1,%2,%3}, {%4,%5,%6,%7}, {%8,%9}, {%0,%1,%2,%3};"
        : "+f"(d[0]), "+f"(d[1]), "+f"(d[2]), "+f"(d[3])
        : "r"(a[0]), "r"(a[1]), "r"(a[2]), "r"(a[3]), "r"(b[0]), "r"(b[1]));
}

// ---------------------------------------------------------------------------
// Kernel 0: transpose x[b][l][c] -> fragment-order d_xT (tf32-rounded)
// ---------------------------------------------------------------------------
__global__ __launch_bounds__(256) void transpose_k(const float* __restrict__ x) {
    __shared__ float sh[8][32][33];     // [c][k][b]
    const int c0 = blockIdx.x * 8;
    const int l0 = blockIdx.y * 32;
    const int b0 = blockIdx.z * 32;
    const int tid = threadIdx.x;
    const float4* x4 = (const float4*)x;
#pragma unroll
    for (int it = 0; it < 8; it++) {
        int i = it * 256 + tid;
        int c4i = i & 1, l = (i >> 1) & 31, b = i >> 6;
        int lg = l0 + l;
        float4 v = make_float4(0.f, 0.f, 0.f, 0.f);
        if (lg < SEQL)
            v = x4[(size_t)(b0 + b) * (SEQL * 16) + (size_t)lg * 16 + (c0 >> 2) + c4i];
        sh[c4i * 4 + 0][l][b] = to_tf32(v.x);
        sh[c4i * 4 + 1][l][b] = to_tf32(v.y);
        sh[c4i * 4 + 2][l][b] = to_tf32(v.z);
        sh[c4i * 4 + 3][l][b] = to_tf32(v.w);
    }
    __syncthreads();
    float4* o4 = (float4*)d_xT;
#pragma unroll
    for (int it = 0; it < 8; it++) {
        int i = it * 256 + tid;
        int lane = i & 31, kbl = (i >> 5) & 3, mbl = (i >> 7) & 1, cl = i >> 8;
        int kb_g = (l0 >> 3) + kbl;
        if (kb_g >= 21) continue;
        int g = lane >> 2, t = lane & 3;
        float4 w;
        w.x = sh[cl][kbl * 8 + t]    [mbl * 16 + g];       // (g,   t)
        w.y = sh[cl][kbl * 8 + t]    [mbl * 16 + g + 8];   // (g+8, t)
        w.z = sh[cl][kbl * 8 + t + 4][mbl * 16 + g];       // (g,   t+4)
        w.w = sh[cl][kbl * 8 + t + 4][mbl * 16 + g + 8];   // (g+8, t+4)
        size_t idx4 = (((size_t)(c0 + cl) * 256 + (b0 >> 4) + mbl) * 21 + kb_g) * 32 + lane;
        o4[idx4] = w;
    }
}

// ---------------------------------------------------------------------------
// Kernel 1: per-batch quantum path -> d_mod[b][p]
// ---------------------------------------------------------------------------
__device__ __forceinline__ float2 cmulf(float2 a, float2 b) {
    return make_float2(a.x * b.x - a.y * b.y, a.x * b.y + a.y * b.x);
}

__device__ void run_circuit(const float qin[4], const float* __restrict__ w, float2 s[16]) {
#pragma unroll
    for (int i = 0; i < 16; i++) s[i] = make_float2(0.f, 0.f);
    s[0].x = 1.f;
#pragma unroll
    for (int l = 0; l < 3; l++) {
#pragma unroll
        for (int q = 0; q < 4; q++) {
            const int m = 8 >> q;
            float sn, cs; sincosf(0.5f * qin[q], &sn, &cs);
#pragma unroll
            for (int i = 0; i < 16; i++) {
                if ((i & m) == 0) {
                    float2 a0 = s[i], a1 = s[i | m];
                    s[i]     = make_float2(cs * a0.x - sn * a1.x, cs * a0.y - sn * a1.y);
                    s[i | m] = make_float2(sn * a0.x + cs * a1.x, sn * a0.y + cs * a1.y);
                }
            }
        }
#pragma unroll
        for (int q = 0; q < 4; q++) {
            const int m = 8 >> q;
            float phi = w[(l * 4 + q) * 3 + 0];
            float th  = w[(l * 4 + q) * 3 + 1];
            float om  = w[(l * 4 + q) * 3 + 2];
            float st, ct; sincosf(0.5f * th, &st, &ct);
            float s1, c1; sincosf(-0.5f * (phi + om), &s1, &c1);
            float s2, c2; sincosf( 0.5f * (phi - om), &s2, &c2);
            float2 U00 = make_float2( c1 * ct,  s1 * ct);
            float2 U01 = make_float2(-c2 * st, -s2 * st);
            float2 U10 = make_float2( c2 * st, -s2 * st);
            float2 U11 = make_float2( c1 * ct, -s1 * ct);
#pragma unroll
            for (int i = 0; i < 16; i++) {
                if ((i & m) == 0) {
                    float2 a0 = s[i], a1 = s[i | m];
                    float2 n0 = cmulf(U00, a0); float2 t = cmulf(U01, a1);
                    n0.x += t.x; n0.y += t.y;
                    float2 n1 = cmulf(U10, a0); t = cmulf(U11, a1);
                    n1.x += t.x; n1.y += t.y;
                    s[i] = n0; s[i | m] = n1;
                }
            }
        }
#pragma unroll
        for (int q = 0; q < 4; q++) {
            const int cm = 8 >> q;
            const int tm = 8 >> ((q + 1) & 3);
#pragma unroll
            for (int i = 0; i < 16; i++) {
                if ((i & cm) && !(i & tm)) {
                    float2 t = s[i]; s[i] = s[i | tm]; s[i | tm] = t;
                }
            }
        }
    }
}

__device__ __forceinline__ void expvals(const float2 s[16], int pauli, float* o) {
#pragma unroll
    for (int q = 0; q < 4; q++) {
        const int m = 8 >> q;
        float acc = 0.f;
#pragma unroll
        for (int i = 0; i < 16; i++) {
            if ((i & m) == 0) {
                float2 a0 = s[i], a1 = s[i | m];
                if (pauli == 0)      acc += a0.x * a1.x + a0.y * a1.y;
                else if (pauli == 1) acc += a0.x * a1.y - a0.y * a1.x;
                else                 acc += a0.x * a0.x + a0.y * a0.y
                                          - a1.x * a1.x - a1.y * a1.y;
            }
        }
        o[q] = (pauli == 2) ? acc : 2.f * acc;
    }
}

__global__ __launch_bounds__(96) void mod_k(const float* __restrict__ x,
                      const float* __restrict__ lagc_W, const float* __restrict__ lagc_b,
                      const float* __restrict__ wx, const float* __restrict__ wy,
                      const float* __restrict__ wz,
                      const float* __restrict__ W1, const float* __restrict__ b1,
                      const float* __restrict__ W2, const float* __restrict__ b2) {
    __shared__ float feats_s[32][13];
    const int bl = threadIdx.x & 31;
    const int r  = threadIdx.x >> 5;
    const int b  = blockIdx.x * 32 + bl;
    const int lags[11] = {167, 166, 165, 164, 163, 162, 145, 144, 143, 1, 0};
    float lag[11];
#pragma unroll
    for (int j = 0; j < 11; j++)
        lag[j] = x[(size_t)b * (SEQL * CF) + lags[j] * CF + (CF - 1)];
    float qin[4];
#pragma unroll
    for (int q = 0; q < 4; q++) {
        float s = lagc_b[q];
#pragma unroll
        for (int j = 0; j < 11; j++) s += lag[j] * lagc_W[q * 11 + j];
        qin[q] = tanhf(s) * PI_F;
    }
    const float* w = (r == 0) ? wx : (r == 1) ? wy : wz;
    float2 st[16];
    float f4[4];
    run_circuit(qin, w, st);
    expvals(st, r, f4);
#pragma unroll
    for (int q = 0; q < 4; q++) feats_s[bl][r * 4 + q] = f4[q];
    __syncthreads();
    float feats[12];
#pragma unroll
    for (int j = 0; j < 12; j++) feats[j] = feats_s[bl][j];
    float h[12];
#pragma unroll
    for (int i = 0; i < 12; i++) {
        float s = b1[i];
#pragma unroll
        for (int j = 0; j < 12; j++) s += feats[j] * W1[i * 12 + j];
        h[i] = fmaxf(s, 0.f);
    }
    for (int pp = 0; pp < 32; pp++) {
        int p = r * 32 + pp;
        float s = b2[p];
#pragma unroll
        for (int i = 0; i < 12; i++) s += h[i] * W2[p * 12 + i];
        d_mod[(size_t)b * NP + p] = tanhf(s);
    }
}

// ---------------------------------------------------------------------------
// Kernel 2: combined matrices -> fragment-order d_MT (tf32-rounded)
// ---------------------------------------------------------------------------
__global__ void prep_k(const float* __restrict__ decomp_w,
                       const float* __restrict__ trend_W, const float* __restrict__ trend_b,
                       const float* __restrict__ seas_W,  const float* __restrict__ seas_b,
                       const float* __restrict__ alpha) {
    const int c = blockIdx.x;
    const int p = blockIdx.y;
    const int j = threadIdx.x;  // 0..167
    __shared__ float ker[KW];
    __shared__ float a_sh;
    if (j == 0) {
        float mx = -1e30f;
        for (int k = 0; k < KW; k++) mx = fmaxf(mx, decomp_w[c * KW + k]);
        float sum = 0.f, e[KW];
        for (int k = 0; k < KW; k++) { e[k] = expf(decomp_w[c * KW + k] - mx); sum += e[k]; }
        for (int k = 0; k < KW; k++) ker[k] = e[k] / sum;
        a_sh = 1.f / (1.f + expf(-alpha[0]));
    }
    __syncthreads();
    const float a = a_sh;
    const float* sW = seas_W + p * SEQL;
    const float* tW = trend_W + p * SEQL;
    float sA = 0.f, sB = 0.f;
    if (j == 0) {
        for (int k = 0; k <= 12; k++) {
            float wk = ker[k];
            for (int l = 0; l <= 12 - k; l++) { sA += wk * sW[l]; sB += wk * tW[l]; }
        }
    } else if (j == SEQL - 1) {
        for (int k = 12; k < KW; k++) {
            float wk = ker[k];
            for (int l = 179 - k; l < SEQL; l++) { sA += wk * sW[l]; sB += wk * tW[l]; }
        }
    } else {
        for (int k = 0; k < KW; k++) {
            int l = j + 12 - k;
            if (l >= 0 && l < SEQL) { float wk = ker[k]; sA += wk * sW[l]; sB += wk * tW[l]; }
        }
    }
    float A = sW[j] - sA;
    float M1 = to_tf32(a * A + (1.f - a) * sB);   // n = 2p
    float M2 = to_tf32(a * A);                    // n = 2p+1
    const int kb = j >> 3, kk = j & 7, t = kk & 3, th = kk >> 2;
#pragma unroll
    for (int h = 0; h < 2; h++) {
        int n = 2 * p + h;
        int np = n >> 4, nn = n & 15, q = nn >> 3, g = nn & 7;
        int lane = g * 4 + t, reg = 2 * q + th;
        d_MT[(((size_t)c * 12 + np) * 21 + kb) * 128 + lane * 4 + reg] = h ? M2 : M1;
    }
    if (c == 0 && j == 0) {
        d_c12[p]      = a * seas_b[p] + (1.f - a) * trend_b[p];
        d_c12[NP + p] = a * seas_b[p];
    }
}

// ---------------------------------------------------------------------------
// Kernel 3: TF32 mma.sync GEMM, fragment-order smem.
// CTA: 256 thr, 8 warps (2m x 4n); tile M=64 x N=192; K chunks of 24 (3 kb).
// 3-stage cp.async, 24KB/stage -> 72KB smem -> 2 CTAs/SM.
// ---------------------------------------------------------------------------
#define STAGE_F4   1536                  // float4 per stage (A 384 + B 1152)
#define STAGE_B    (STAGE_F4 * 16)       // 24576 bytes
#define NSTAGE     3

__global__ __launch_bounds__(256, 2) void gemm_k(float* __restrict__ out) {
    extern __shared__ __align__(16) float4 sm4[];
    const int c   = blockIdx.x;          // c fastest -> L2 write merging
    const int b0  = blockIdx.y * 64;
    const int tid = threadIdx.x;
    const int wid  = tid >> 5;
    const int lane = tid & 31;
    const int gid  = lane >> 2;
    const int tig  = lane & 3;
    const int warp_mb = (wid & 1) * 2;   // m16-block base within CTA (0 or 2)
    const int warp_np = (wid >> 1) * 3;  // n16-pair base (0,3,6,9)

    const uint32_t smb = smem_u32(sm4);
    const float4* A4 = (const float4*)d_xT + ((size_t)c * 256 + (b0 >> 4)) * (21 * 32);
    const float4* B4 = (const float4*)d_MT + (size_t)c * 12 * (21 * 32);

    auto load_stage = [&](int s, int kc) {
        const int kb0 = kc * 3;
        const uint32_t D0 = smb + s * STAGE_B;
#pragma unroll
        for (int jj = 0; jj < 6; jj++) {
            int idx4 = jj * 256 + tid;
            const float4* src;
            if (idx4 < 384) {
                int blk = idx4 >> 5, l4 = idx4 & 31;
                int mbl = blk / 3, kbl = blk - mbl * 3;
                src = A4 + ((size_t)mbl * 21 + kb0 + kbl) * 32 + l4;
            } else {
                int j2 = idx4 - 384;
                int blk = j2 >> 5, l4 = j2 & 31;
                int np = blk / 3, kbl = blk - np * 3;
                src = B4 + ((size_t)np * 21 + kb0 + kbl) * 32 + l4;
            }
            cp16(D0 + idx4 * 16, src);
        }
    };

    float acc[2][6][4];
#pragma unroll
    for (int mi = 0; mi < 2; mi++)
#pragma unroll
        for (int ni = 0; ni < 6; ni++)
#pragma unroll
            for (int r = 0; r < 4; r++) acc[mi][ni][r] = 0.f;

    load_stage(0, 0);
    asm volatile("cp.async.commit_group;" ::: "memory");
    load_stage(1, 1);
    asm volatile("cp.async.commit_group;" ::: "memory");
    load_stage(2, 2);
    asm volatile("cp.async.commit_group;" ::: "memory");

    int s = 0;
    for (int kc = 0; kc < 7; kc++) {
        asm volatile("cp.async.wait_group 2;" ::: "memory");
        __syncthreads();
        const float4* As = sm4 + s * STAGE_F4;
        const float4* Bs = As + 384;
#pragma unroll
        for (int kbl = 0; kbl < 3; kbl++) {
            float4 af4[2], bf4[3];
#pragma unroll
            for (int mi = 0; mi < 2; mi++)
                af4[mi] = As[((warp_mb + mi) * 3 + kbl) * 32 + lane];
#pragma unroll
            for (int npj = 0; npj < 3; npj++)
                bf4[npj] = Bs[((warp_np + npj) * 3 + kbl) * 32 + lane];
#pragma unroll
            for (int mi = 0; mi < 2; mi++) {
                const uint32_t* a = (const uint32_t*)&af4[mi];
#pragma unroll
                for (int npj = 0; npj < 3; npj++) {
                    const uint32_t* b = (const uint32_t*)&bf4[npj];
                    mma_tf32(acc[mi][npj * 2 + 0], a, b);       // nblock even
                    mma_tf32(acc[mi][npj * 2 + 1], a, b + 2);   // nblock odd
                }
            }
        }
        __syncthreads();
        if (kc + 3 < 7) load_stage(s, kc + 3);
        asm volatile("cp.async.commit_group;" ::: "memory");
        s = (s == NSTAGE - 1) ? 0 : s + 1;
    }

    // epilogue: p = warp_np*8 + ni*4 + tig; b = b0 + (wid&1)*32 + mi*16 + gid + h*8
    const int pbase = warp_np * 8;
#pragma unroll
    for (int ni = 0; ni < 6; ni++) {
        const int p = pbase + ni * 4 + tig;
        const float C1 = d_c12[p];
        const float C2 = d_c12[NP + p];
#pragma unroll
        for (int mi = 0; mi < 2; mi++) {
#pragma unroll
            for (int h = 0; h < 2; h++) {
                const int b = b0 + (wid & 1) * 32 + mi * 16 + gid + h * 8;
                const float y1 = acc[mi][ni][2 * h];
                const float y2 = acc[mi][ni][2 * h + 1];
                const float m = d_mod[(size_t)b * NP + p];
                out[(size_t)b * (NP * CF) + (size_t)p * CF + c] =
                    y1 + C1 + m * (y2 + C2);
            }
        }
    }
}

// ---------------------------------------------------------------------------
extern "C" void kernel_launch(void* const* d_in, const int* in_sizes, int n_in,
                              void* d_out, int out_size) {
    const float* x        = (const float*)d_in[0];
    const float* decomp_w = (const float*)d_in[1];
    const float* trend_W  = (const float*)d_in[2];
    const float* trend_b  = (const float*)d_in[3];
    const float* seas_W   = (const float*)d_in[4];
    const float* seas_b   = (const float*)d_in[5];
    const float* lagc_W   = (const float*)d_in[6];
    const float* lagc_b   = (const float*)d_in[7];
    const float* wx       = (const float*)d_in[8];
    const float* wy       = (const float*)d_in[9];
    const float* wz       = (const float*)d_in[10];
    const float* W1       = (const float*)d_in[11];
    const float* b1       = (const float*)d_in[12];
    const float* W2       = (const float*)d_in[13];
    const float* b2       = (const float*)d_in[14];
    const float* alpha    = (const float*)d_in[15];
    float* out = (float*)d_out;

    cudaFuncSetAttribute(gemm_k, cudaFuncAttributeMaxDynamicSharedMemorySize,
                         NSTAGE * STAGE_B);

    transpose_k<<<dim3(8, 6, 128), 256>>>(x);
    mod_k<<<128, 96>>>(x, lagc_W, lagc_b, wx, wy, wz, W1, b1, W2, b2);
    prep_k<<<dim3(64, 96), 168>>>(decomp_w, trend_W, trend_b, seas_W, seas_b, alpha);
    gemm_k<<<dim3(64, 64), 256, NSTAGE * STAGE_B>>>(out);
}

// round 7
// speedup vs baseline: 1.7082x; 1.0016x over previous
#include <cuda_runtime.h>
#include <math.h>
#include <stdint.h>

#define NB    4096
#define SEQL  168
#define CF    64
#define NP    96
#define KW    25
#define PI_F  3.14159265358979f

// fragment-order scratch:
// d_xT: [c][mb(256)][kb(21)][128]  (m16xk8 fragment blocks, lane*4+reg)
// d_MT: [c][np(12)][kb(21)][128]   (n16xk8 fragment blocks: 2 n8 blocks/pair)
__device__ float d_xT[(size_t)CF * 256 * 21 * 128];
__device__ float d_MT[(size_t)CF * 12 * 21 * 128];
__device__ float d_mod[(size_t)NB * NP];
__device__ float d_c12[2 * NP];

__device__ __forceinline__ float to_tf32(float f) {
    uint32_t u;
    asm("cvt.rna.tf32.f32 %0, %1;" : "=r"(u) : "f"(f));
    return __uint_as_float(u);
}
__device__ __forceinline__ uint32_t smem_u32(const void* p) {
    uint32_t a;
    asm("{ .reg .u64 t; cvta.to.shared.u64 t, %1; cvt.u32.u64 %0, t; }" : "=r"(a) : "l"(p));
    return a;
}
__device__ __forceinline__ void cp16(uint32_t dst, const void* src) {
    asm volatile("cp.async.cg.shared.global [%0], [%1], 16;" :: "r"(dst), "l"(src));
}
__device__ __forceinline__ void mma_tf32(float* d, const uint32_t* a, const uint32_t* b) {
    asm volatile(
        "mma.sync.aligned.m16n8k8.row.col.f32.tf32.tf32.f32 "
        "{%0,%1,%2,%3}, {%4,%5,%6,%7}, {%8,%9}, {%0,%1,%2,%3};"
        : "+f"(d[0]), "+f"(d[1]), "+f"(d[2]), "+f"(d[3])
        : "r"(a[0]), "r"(a[1]), "r"(a[2]), "r"(a[3]), "r"(b[0]), "r"(b[1]));
}
__device__ __forceinline__ void mbar_init(uint32_t a, uint32_t cnt) {
    asm volatile("mbarrier.init.shared.b64 [%0], %1;" :: "r"(a), "r"(cnt) : "memory");
}
__device__ __forceinline__ void mbar_wait(uint32_t a, uint32_t parity) {
    asm volatile(
        "{\n\t.reg .pred P;\n\t"
        "WL_%=:\n\t"
        "mbarrier.try_wait.parity.acquire.cta.shared::cta.b64 P, [%0], %1, 0x989680;\n\t"
        "@!P bra WL_%=;\n\t}"
        :: "r"(a), "r"(parity) : "memory");
}
__device__ __forceinline__ void mbar_arrive(uint32_t a) {
    asm volatile("mbarrier.arrive.release.cta.shared::cta.b64 _, [%0];" :: "r"(a) : "memory");
}
// .noinc is load-bearing: the default form pre-increments the pending count
// (net zero); .noinc makes each arrival decrement the initialized count of 32.
__device__ __forceinline__ void cpasync_arrive(uint32_t a) {
    asm volatile("cp.async.mbarrier.arrive.noinc.shared::cta.b64 [%0];" :: "r"(a) : "memory");
}

// ---------------------------------------------------------------------------
// Kernel 0: transpose x[b][l][c] -> fragment-order d_xT (tf32-rounded)
// ---------------------------------------------------------------------------
__global__ __launch_bounds__(256) void transpose_k(const float* __restrict__ x) {
    __shared__ float sh[8][32][33];     // [c][k][b]
    const int c0 = blockIdx.x * 8;
    const int l0 = blockIdx.y * 32;
    const int b0 = blockIdx.z * 32;
    const int tid = threadIdx.x;
    const float4* x4 = (const float4*)x;
#pragma unroll
    for (int it = 0; it < 8; it++) {
        int i = it * 256 + tid;
        int c4i = i & 1, l = (i >> 1) & 31, b = i >> 6;
        int lg = l0 + l;
        float4 v = make_float4(0.f, 0.f, 0.f, 0.f);
        if (lg < SEQL)
            v = x4[(size_t)(b0 + b) * (SEQL * 16) + (size_t)lg * 16 + (c0 >> 2) + c4i];
        sh[c4i * 4 + 0][l][b] = to_tf32(v.x);
        sh[c4i * 4 + 1][l][b] = to_tf32(v.y);
        sh[c4i * 4 + 2][l][b] = to_tf32(v.z);
        sh[c4i * 4 + 3][l][b] = to_tf32(v.w);
    }
    __syncthreads();
    float4* o4 = (float4*)d_xT;
#pragma unroll
    for (int it = 0; it < 8; it++) {
        int i = it * 256 + tid;
        int lane = i & 31, kbl = (i >> 5) & 3, mbl = (i >> 7) & 1, cl = i >> 8;
        int kb_g = (l0 >> 3) + kbl;
        if (kb_g >= 21) continue;
        int g = lane >> 2, t = lane & 3;
        float4 w;
        w.x = sh[cl][kbl * 8 + t]    [mbl * 16 + g];       // (g,   t)
        w.y = sh[cl][kbl * 8 + t]    [mbl * 16 + g + 8];   // (g+8, t)
        w.z = sh[cl][kbl * 8 + t + 4][mbl * 16 + g];       // (g,   t+4)
        w.w = sh[cl][kbl * 8 + t + 4][mbl * 16 + g + 8];   // (g+8, t+4)
        size_t idx4 = (((size_t)(c0 + cl) * 256 + (b0 >> 4) + mbl) * 21 + kb_g) * 32 + lane;
        o4[idx4] = w;
    }
}

// ---------------------------------------------------------------------------
// Kernel 1: per-batch quantum path -> d_mod[b][p]
// ---------------------------------------------------------------------------
__device__ __forceinline__ float2 cmulf(float2 a, float2 b) {
    return make_float2(a.x * b.x - a.y * b.y, a.x * b.y + a.y * b.x);
}

__device__ void run_circuit(const float qin[4], const float* __restrict__ w, float2 s[16]) {
#pragma unroll
    for (int i = 0; i < 16; i++) s[i] = make_float2(0.f, 0.f);
    s[0].x = 1.f;
#pragma unroll
    for (int l = 0; l < 3; l++) {
#pragma unroll
        for (int q = 0; q < 4; q++) {
            const int m = 8 >> q;
            float sn, cs; sincosf(0.5f * qin[q], &sn, &cs);
#pragma unroll
            for (int i = 0; i < 16; i++) {
                if ((i & m) == 0) {
                    float2 a0 = s[i], a1 = s[i | m];
                    s[i]     = make_float2(cs * a0.x - sn * a1.x, cs * a0.y - sn * a1.y);
                    s[i | m] = make_float2(sn * a0.x + cs * a1.x, sn * a0.y + cs * a1.y);
                }
            }
        }
#pragma unroll
        for (int q = 0; q < 4; q++) {
            const int m = 8 >> q;
            float phi = w[(l * 4 + q) * 3 + 0];
            float th  = w[(l * 4 + q) * 3 + 1];
            float om  = w[(l * 4 + q) * 3 + 2];
            float st, ct; sincosf(0.5f * th, &st, &ct);
            float s1, c1; sincosf(-0.5f * (phi + om), &s1, &c1);
            float s2, c2; sincosf( 0.5f * (phi - om), &s2, &c2);
            float2 U00 = make_float2( c1 * ct,  s1 * ct);
            float2 U01 = make_float2(-c2 * st, -s2 * st);
            float2 U10 = make_float2( c2 * st, -s2 * st);
            float2 U11 = make_float2( c1 * ct, -s1 * ct);
#pragma unroll
            for (int i = 0; i < 16; i++) {
                if ((i & m) == 0) {
                    float2 a0 = s[i], a1 = s[i | m];
                    float2 n0 = cmulf(U00, a0); float2 t = cmulf(U01, a1);
                    n0.x += t.x; n0.y += t.y;
                    float2 n1 = cmulf(U10, a0); t = cmulf(U11, a1);
                    n1.x += t.x; n1.y += t.y;
                    s[i] = n0; s[i | m] = n1;
                }
            }
        }
#pragma unroll
        for (int q = 0; q < 4; q++) {
            const int cm = 8 >> q;
            const int tm = 8 >> ((q + 1) & 3);
#pragma unroll
            for (int i = 0; i < 16; i++) {
                if ((i & cm) && !(i & tm)) {
                    float2 t = s[i]; s[i] = s[i | tm]; s[i | tm] = t;
                }
            }
        }
    }
}

__device__ __forceinline__ void expvals(const float2 s[16], int pauli, float* o) {
#pragma unroll
    for (int q = 0; q < 4; q++) {
        const int m = 8 >> q;
        float acc = 0.f;
#pragma unroll
        for (int i = 0; i < 16; i++) {
            if ((i & m) == 0) {
                float2 a0 = s[i], a1 = s[i | m];
                if (pauli == 0)      acc += a0.x * a1.x + a0.y * a1.y;
                else if (pauli == 1) acc += a0.x * a1.y - a0.y * a1.x;
                else                 acc += a0.x * a0.x + a0.y * a0.y
                                          - a1.x * a1.x - a1.y * a1.y;
            }
        }
        o[q] = (pauli == 2) ? acc : 2.f * acc;
    }
}

__global__ __launch_bounds__(96) void mod_k(const float* __restrict__ x,
                      const float* __restrict__ lagc_W, const float* __restrict__ lagc_b,
                      const float* __restrict__ wx, const float* __restrict__ wy,
                      const float* __restrict__ wz,
                      const float* __restrict__ W1, const float* __restrict__ b1,
                      const float* __restrict__ W2, const float* __restrict__ b2) {
    __shared__ float feats_s[32][13];
    const int bl = threadIdx.x & 31;
    const int r  = threadIdx.x >> 5;
    const int b  = blockIdx.x * 32 + bl;
    const int lags[11] = {167, 166, 165, 164, 163, 162, 145, 144, 143, 1, 0};
    float lag[11];
#pragma unroll
    for (int j = 0; j < 11; j++)
        lag[j] = x[(size_t)b * (SEQL * CF) + lags[j] * CF + (CF - 1)];
    float qin[4];
#pragma unroll
    for (int q = 0; q < 4; q++) {
        float s = lagc_b[q];
#pragma unroll
        for (int j = 0; j < 11; j++) s += lag[j] * lagc_W[q * 11 + j];
        qin[q] = tanhf(s) * PI_F;
    }
    const float* w = (r == 0) ? wx : (r == 1) ? wy : wz;
    float2 st[16];
    float f4[4];
    run_circuit(qin, w, st);
    expvals(st, r, f4);
#pragma unroll
    for (int q = 0; q < 4; q++) feats_s[bl][r * 4 + q] = f4[q];
    __syncthreads();
    float feats[12];
#pragma unroll
    for (int j = 0; j < 12; j++) feats[j] = feats_s[bl][j];
    float h[12];
#pragma unroll
    for (int i = 0; i < 12; i++) {
        float s = b1[i];
#pragma unroll
        for (int j = 0; j < 12; j++) s += feats[j] * W1[i * 12 + j];
        h[i] = fmaxf(s, 0.f);
    }
    for (int pp = 0; pp < 32; pp++) {
        int p = r * 32 + pp;
        float s = b2[p];
#pragma unroll
        for (int i = 0; i < 12; i++) s += h[i] * W2[p * 12 + i];
        d_mod[(size_t)b * NP + p] = tanhf(s);
    }
}

// ---------------------------------------------------------------------------
// Kernel 2: combined matrices -> fragment-order d_MT (tf32-rounded)
// ---------------------------------------------------------------------------
__global__ void prep_k(const float* __restrict__ decomp_w,
                       const float* __restrict__ trend_W, const float* __restrict__ trend_b,
                       const float* __restrict__ seas_W,  const float* __restrict__ seas_b,
                       const float* __restrict__ alpha) {
    const int c = blockIdx.x;
    const int p = blockIdx.y;
    const int j = threadIdx.x;  // 0..167
    __shared__ float ker[KW];
    __shared__ float a_sh;
    if (j == 0) {
        float mx = -1e30f;
        for (int k = 0; k < KW; k++) mx = fmaxf(mx, decomp_w[c * KW + k]);
        float sum = 0.f, e[KW];
        for (int k = 0; k < KW; k++) { e[k] = expf(decomp_w[c * KW + k] - mx); sum += e[k]; }
        for (int k = 0; k < KW; k++) ker[k] = e[k] / sum;
        a_sh = 1.f / (1.f + expf(-alpha[0]));
    }
    __syncthreads();
    const float a = a_sh;
    const float* sW = seas_W + p * SEQL;
    const float* tW = trend_W + p * SEQL;
    float sA = 0.f, sB = 0.f;
    if (j == 0) {
        for (int k = 0; k <= 12; k++) {
            float wk = ker[k];
            for (int l = 0; l <= 12 - k; l++) { sA += wk * sW[l]; sB += wk * tW[l]; }
        }
    } else if (j == SEQL - 1) {
        for (int k = 12; k < KW; k++) {
            float wk = ker[k];
            for (int l = 179 - k; l < SEQL; l++) { sA += wk * sW[l]; sB += wk * tW[l]; }
        }
    } else {
        for (int k = 0; k < KW; k++) {
            int l = j + 12 - k;
            if (l >= 0 && l < SEQL) { float wk = ker[k]; sA += wk * sW[l]; sB += wk * tW[l]; }
        }
    }
    float A = sW[j] - sA;
    float M1 = to_tf32(a * A + (1.f - a) * sB);   // n = 2p
    float M2 = to_tf32(a * A);                    // n = 2p+1
    const int kb = j >> 3, kk = j & 7, t = kk & 3, th = kk >> 2;
#pragma unroll
    for (int h = 0; h < 2; h++) {
        int n = 2 * p + h;
        int np = n >> 4, nn = n & 15, q = nn >> 3, g = nn & 7;
        int lane = g * 4 + t, reg = 2 * q + th;
        d_MT[(((size_t)c * 12 + np) * 21 + kb) * 128 + lane * 4 + reg] = h ? M2 : M1;
    }
    if (c == 0 && j == 0) {
        d_c12[p]      = a * seas_b[p] + (1.f - a) * trend_b[p];
        d_c12[NP + p] = a * seas_b[p];
    }
}

// ---------------------------------------------------------------------------
// Kernel 3: TF32 mma.sync GEMM, warp-specialized producer/consumer.
// 288 threads: warps 0-7 consumers (2m x 4n, warp tile m32 x n48),
// warp 8 producer (all cp.async). 4 stages x 24KB, mbarrier-gated,
// NO __syncthreads in mainloop. 2 CTAs/SM.
// ---------------------------------------------------------------------------
#define STAGE_F4   1536                  // float4 per stage (A 384 + B 1152)
#define STAGE_B    (STAGE_F4 * 16)       // 24576 bytes
#define NSTAGE     4
#define NCHUNK     7

__global__ __launch_bounds__(288, 2) void gemm_k(float* __restrict__ out) {
    extern __shared__ __align__(16) float4 sm4[];
    __shared__ __align__(8) uint64_t mbar[2 * NSTAGE];   // full[0..3], empty[0..3]

    const int c   = blockIdx.x;          // c fastest -> L2 write merging
    const int b0  = blockIdx.y * 64;
    const int tid = threadIdx.x;
    const int wid  = tid >> 5;
    const int lane = tid & 31;

    const uint32_t smb = smem_u32(sm4);
    const uint32_t mbF = smem_u32(&mbar[0]);
    const uint32_t mbE = smem_u32(&mbar[NSTAGE]);

    if (tid == 0) {
#pragma unroll
        for (int s = 0; s < NSTAGE; s++) {
            mbar_init(mbF + 8 * s, 32);  // producer cp.async .noinc arrivals
            mbar_init(mbE + 8 * s, 8);   // one arrive per consumer warp
        }
    }
    __syncthreads();

    if (wid == 8) {
        // ---- producer warp ----
        const float4* A4 = (const float4*)d_xT + ((size_t)c * 256 + (b0 >> 4)) * (21 * 32);
        const float4* B4 = (const float4*)d_MT + (size_t)c * 12 * (21 * 32);
        for (int kc = 0; kc < NCHUNK; kc++) {
            const int s = kc & (NSTAGE - 1);
            if (kc >= NSTAGE) mbar_wait(mbE + 8 * s, ((kc >> 2) - 1) & 1);
            const int kb0 = kc * 3;
            const uint32_t D0 = smb + s * STAGE_B;
#pragma unroll
            for (int j = 0; j < 48; j++) {
                int idx4 = j * 32 + lane;
                const float4* src;
                if (idx4 < 384) {
                    int blk = idx4 >> 5, l4 = idx4 & 31;
                    int mbl = blk / 3, kbl = blk - mbl * 3;
                    src = A4 + ((size_t)mbl * 21 + kb0 + kbl) * 32 + l4;
                } else {
                    int j2 = idx4 - 384;
                    int blk = j2 >> 5, l4 = j2 & 31;
                    int np = blk / 3, kbl = blk - np * 3;
                    src = B4 + ((size_t)np * 21 + kb0 + kbl) * 32 + l4;
                }
                cp16(D0 + idx4 * 16, src);
            }
            cpasync_arrive(mbF + 8 * s);
        }
    } else {
        // ---- consumer warps 0..7 ----
        const int warp_mb = (wid & 1) * 2;   // m16-block base (0 or 2)
        const int warp_np = (wid >> 1) * 3;  // n16-pair base (0,3,6,9)

        float acc[2][6][4];
#pragma unroll
        for (int mi = 0; mi < 2; mi++)
#pragma unroll
            for (int ni = 0; ni < 6; ni++)
#pragma unroll
                for (int r = 0; r < 4; r++) acc[mi][ni][r] = 0.f;

        for (int kc = 0; kc < NCHUNK; kc++) {
            const int s = kc & (NSTAGE - 1);
            mbar_wait(mbF + 8 * s, (kc >> 2) & 1);
            const float4* As = sm4 + s * STAGE_F4;
            const float4* Bs = As + 384;
#pragma unroll
            for (int kbl = 0; kbl < 3; kbl++) {
                float4 af4[2], bf4[3];
#pragma unroll
                for (int mi = 0; mi < 2; mi++)
                    af4[mi] = As[((warp_mb + mi) * 3 + kbl) * 32 + lane];
#pragma unroll
                for (int npj = 0; npj < 3; npj++)
                    bf4[npj] = Bs[((warp_np + npj) * 3 + kbl) * 32 + lane];
#pragma unroll
                for (int mi = 0; mi < 2; mi++) {
                    const uint32_t* a = (const uint32_t*)&af4[mi];
#pragma unroll
                    for (int npj = 0; npj < 3; npj++) {
                        const uint32_t* b = (const uint32_t*)&bf4[npj];
                        mma_tf32(acc[mi][npj * 2 + 0], a, b);
                        mma_tf32(acc[mi][npj * 2 + 1], a, b + 2);
                    }
                }
            }
            if (lane == 0) mbar_arrive(mbE + 8 * s);
        }

        // epilogue
        const int gid = lane >> 2;
        const int tig = lane & 3;
        const int pbase = warp_np * 8;
#pragma unroll
        for (int ni = 0; ni < 6; ni++) {
            const int p = pbase + ni * 4 + tig;
            const float C1 = d_c12[p];
            const float C2 = d_c12[NP + p];
#pragma unroll
            for (int mi = 0; mi < 2; mi++) {
#pragma unroll
                for (int h = 0; h < 2; h++) {
                    const int b = b0 + (wid & 1) * 32 + mi * 16 + gid + h * 8;
                    const float y1 = acc[mi][ni][2 * h];
                    const float y2 = acc[mi][ni][2 * h + 1];
                    const float m = d_mod[(size_t)b * NP + p];
                    out[(size_t)b * (NP * CF) + (size_t)p * CF + c] =
                        y1 + C1 + m * (y2 + C2);
                }
            }
        }
    }
}

// ---------------------------------------------------------------------------
extern "C" void kernel_launch(void* const* d_in, const int* in_sizes, int n_in,
                              void* d_out, int out_size) {
    const float* x        = (const float*)d_in[0];
    const float* decomp_w = (const float*)d_in[1];
    const float* trend_W  = (const float*)d_in[2];
    const float* trend_b  = (const float*)d_in[3];
    const float* seas_W   = (const float*)d_in[4];
    const float* seas_b   = (const float*)d_in[5];
    const float* lagc_W   = (const float*)d_in[6];
    const float* lagc_b   = (const float*)d_in[7];
    const float* wx       = (const float*)d_in[8];
    const float* wy       = (const float*)d_in[9];
    const float* wz       = (const float*)d_in[10];
    const float* W1       = (const float*)d_in[11];
    const float* b1       = (const float*)d_in[12];
    const float* W2       = (const float*)d_in[13];
    const float* b2       = (const float*)d_in[14];
    const float* alpha    = (const float*)d_in[15];
    float* out = (float*)d_out;

    cudaFuncSetAttribute(gemm_k, cudaFuncAttributeMaxDynamicSharedMemorySize,
                         NSTAGE * STAGE_B);

    transpose_k<<<dim3(8, 6, 128), 256>>>(x);
    mod_k<<<128, 96>>>(x, lagc_W, lagc_b, wx, wy, wz, W1, b1, W2, b2);
    prep_k<<<dim3(64, 96), 168>>>(decomp_w, trend_W, trend_b, seas_W, seas_b, alpha);
    gemm_k<<<dim3(64, 64), 288, NSTAGE * STAGE_B>>>(out);
}

// round 8
// speedup vs baseline: 1.9851x; 1.1621x over previous
#include <cuda_runtime.h>
#include <math.h>
#include <stdint.h>

#define NB    4096
#define SEQL  168
#define CF    64
#define NP    96
#define KW    25
#define PI_F  3.14159265358979f

// fragment-order scratch:
// d_xT: [c][mb(256)][kb(21)][128]  (m16xk8 fragment blocks, lane*4+reg)
// d_MT: [c][np(12)][kb(21)][128]   (n16xk8 fragment blocks: 2 n8 blocks/pair)
__device__ float d_xT[(size_t)CF * 256 * 21 * 128];
__device__ float d_MT[(size_t)CF * 12 * 21 * 128];
__device__ float d_modT[(size_t)NP * NB];            // [p][b] (coalesced reads)
__device__ float d_outS[(size_t)CF * NP * NB];       // [c][p][b] gemm scratch (100MB)
__device__ float d_c12[2 * NP];

__device__ __forceinline__ float to_tf32(float f) {
    uint32_t u;
    asm("cvt.rna.tf32.f32 %0, %1;" : "=r"(u) : "f"(f));
    return __uint_as_float(u);
}
__device__ __forceinline__ uint32_t smem_u32(const void* p) {
    uint32_t a;
    asm("{ .reg .u64 t; cvta.to.shared.u64 t, %1; cvt.u32.u64 %0, t; }" : "=r"(a) : "l"(p));
    return a;
}
__device__ __forceinline__ void cp16(uint32_t dst, const void* src) {
    asm volatile("cp.async.cg.shared.global [%0], [%1], 16;" :: "r"(dst), "l"(src));
}
__device__ __forceinline__ void mma_tf32(float* d, const uint32_t* a, const uint32_t* b) {
    asm volatile(
        "mma.sync.aligned.m16n8k8.row.col.f32.tf32.tf32.f32 "
        "{%0,%1,%2,%3}, {%4,%5,%6,%7}, {%8,%9}, {%0,%1,%2,%3};"
        : "+f"(d[0]), "+f"(d[1]), "+f"(d[2]), "+f"(d[3])
        : "r"(a[0]), "r"(a[1]), "r"(a[2]), "r"(a[3]), "r"(b[0]), "r"(b[1]));
}
__device__ __forceinline__ void mbar_init(uint32_t a, uint32_t cnt) {
    asm volatile("mbarrier.init.shared.b64 [%0], %1;" :: "r"(a), "r"(cnt) : "memory");
}
__device__ __forceinline__ void mbar_wait(uint32_t a, uint32_t parity) {
    asm volatile(
        "{\n\t.reg .pred P;\n\t"
        "WL_%=:\n\t"
        "mbarrier.try_wait.parity.acquire.cta.shared::cta.b64 P, [%0], %1, 0x989680;\n\t"
        "@!P bra WL_%=;\n\t}"
        :: "r"(a), "r"(parity) : "memory");
}
// .noinc: each cp.async-group arrival decrements the initialized count.
__device__ __forceinline__ void cpasync_arrive(uint32_t a) {
    asm volatile("cp.async.mbarrier.arrive.noinc.shared::cta.b64 [%0];" :: "r"(a) : "memory");
}

// ---------------------------------------------------------------------------
// Kernel 0: transpose x[b][l][c] -> fragment-order d_xT (tf32-rounded)
// ---------------------------------------------------------------------------
__global__ __launch_bounds__(256) void transpose_k(const float* __restrict__ x) {
    __shared__ float sh[8][32][33];     // [c][k][b]
    const int c0 = blockIdx.x * 8;
    const int l0 = blockIdx.y * 32;
    const int b0 = blockIdx.z * 32;
    const int tid = threadIdx.x;
    const float4* x4 = (const float4*)x;
#pragma unroll
    for (int it = 0; it < 8; it++) {
        int i = it * 256 + tid;
        int c4i = i & 1, l = (i >> 1) & 31, b = i >> 6;
        int lg = l0 + l;
        float4 v = make_float4(0.f, 0.f, 0.f, 0.f);
        if (lg < SEQL)
            v = x4[(size_t)(b0 + b) * (SEQL * 16) + (size_t)lg * 16 + (c0 >> 2) + c4i];
        sh[c4i * 4 + 0][l][b] = to_tf32(v.x);
        sh[c4i * 4 + 1][l][b] = to_tf32(v.y);
        sh[c4i * 4 + 2][l][b] = to_tf32(v.z);
        sh[c4i * 4 + 3][l][b] = to_tf32(v.w);
    }
    __syncthreads();
    float4* o4 = (float4*)d_xT;
#pragma unroll
    for (int it = 0; it < 8; it++) {
        int i = it * 256 + tid;
        int lane = i & 31, kbl = (i >> 5) & 3, mbl = (i >> 7) & 1, cl = i >> 8;
        int kb_g = (l0 >> 3) + kbl;
        if (kb_g >= 21) continue;
        int g = lane >> 2, t = lane & 3;
        float4 w;
        w.x = sh[cl][kbl * 8 + t]    [mbl * 16 + g];       // (g,   t)
        w.y = sh[cl][kbl * 8 + t]    [mbl * 16 + g + 8];   // (g+8, t)
        w.z = sh[cl][kbl * 8 + t + 4][mbl * 16 + g];       // (g,   t+4)
        w.w = sh[cl][kbl * 8 + t + 4][mbl * 16 + g + 8];   // (g+8, t+4)
        size_t idx4 = (((size_t)(c0 + cl) * 256 + (b0 >> 4) + mbl) * 21 + kb_g) * 32 + lane;
        o4[idx4] = w;
    }
}

// ---------------------------------------------------------------------------
// Kernel 1: per-batch quantum path -> d_modT[p][b]
// ---------------------------------------------------------------------------
__device__ __forceinline__ float2 cmulf(float2 a, float2 b) {
    return make_float2(a.x * b.x - a.y * b.y, a.x * b.y + a.y * b.x);
}

__device__ void run_circuit(const float qin[4], const float* __restrict__ w, float2 s[16]) {
#pragma unroll
    for (int i = 0; i < 16; i++) s[i] = make_float2(0.f, 0.f);
    s[0].x = 1.f;
#pragma unroll
    for (int l = 0; l < 3; l++) {
#pragma unroll
        for (int q = 0; q < 4; q++) {
            const int m = 8 >> q;
            float sn, cs; sincosf(0.5f * qin[q], &sn, &cs);
#pragma unroll
            for (int i = 0; i < 16; i++) {
                if ((i & m) == 0) {
                    float2 a0 = s[i], a1 = s[i | m];
                    s[i]     = make_float2(cs * a0.x - sn * a1.x, cs * a0.y - sn * a1.y);
                    s[i | m] = make_float2(sn * a0.x + cs * a1.x, sn * a0.y + cs * a1.y);
                }
            }
        }
#pragma unroll
        for (int q = 0; q < 4; q++) {
            const int m = 8 >> q;
            float phi = w[(l * 4 + q) * 3 + 0];
            float th  = w[(l * 4 + q) * 3 + 1];
            float om  = w[(l * 4 + q) * 3 + 2];
            float st, ct; sincosf(0.5f * th, &st, &ct);
            float s1, c1; sincosf(-0.5f * (phi + om), &s1, &c1);
            float s2, c2; sincosf( 0.5f * (phi - om), &s2, &c2);
            float2 U00 = make_float2( c1 * ct,  s1 * ct);
            float2 U01 = make_float2(-c2 * st, -s2 * st);
            float2 U10 = make_float2( c2 * st, -s2 * st);
            float2 U11 = make_float2( c1 * ct, -s1 * ct);
#pragma unroll
            for (int i = 0; i < 16; i++) {
                if ((i & m) == 0) {
                    float2 a0 = s[i], a1 = s[i | m];
                    float2 n0 = cmulf(U00, a0); float2 t = cmulf(U01, a1);
                    n0.x += t.x; n0.y += t.y;
                    float2 n1 = cmulf(U10, a0); t = cmulf(U11, a1);
                    n1.x += t.x; n1.y += t.y;
                    s[i] = n0; s[i | m] = n1;
                }
            }
        }
#pragma unroll
        for (int q = 0; q < 4; q++) {
            const int cm = 8 >> q;
            const int tm = 8 >> ((q + 1) & 3);
#pragma unroll
            for (int i = 0; i < 16; i++) {
                if ((i & cm) && !(i & tm)) {
                    float2 t = s[i]; s[i] = s[i | tm]; s[i | tm] = t;
                }
            }
        }
    }
}

__device__ __forceinline__ void expvals(const float2 s[16], int pauli, float* o) {
#pragma unroll
    for (int q = 0; q < 4; q++) {
        const int m = 8 >> q;
        float acc = 0.f;
#pragma unroll
        for (int i = 0; i < 16; i++) {
            if ((i & m) == 0) {
                float2 a0 = s[i], a1 = s[i | m];
                if (pauli == 0)      acc += a0.x * a1.x + a0.y * a1.y;
                else if (pauli == 1) acc += a0.x * a1.y - a0.y * a1.x;
                else                 acc += a0.x * a0.x + a0.y * a0.y
                                          - a1.x * a1.x - a1.y * a1.y;
            }
        }
        o[q] = (pauli == 2) ? acc : 2.f * acc;
    }
}

__global__ __launch_bounds__(96) void mod_k(const float* __restrict__ x,
                      const float* __restrict__ lagc_W, const float* __restrict__ lagc_b,
                      const float* __restrict__ wx, const float* __restrict__ wy,
                      const float* __restrict__ wz,
                      const float* __restrict__ W1, const float* __restrict__ b1,
                      const float* __restrict__ W2, const float* __restrict__ b2) {
    __shared__ float feats_s[32][13];
    const int bl = threadIdx.x & 31;
    const int r  = threadIdx.x >> 5;
    const int b  = blockIdx.x * 32 + bl;
    const int lags[11] = {167, 166, 165, 164, 163, 162, 145, 144, 143, 1, 0};
    float lag[11];
#pragma unroll
    for (int j = 0; j < 11; j++)
        lag[j] = x[(size_t)b * (SEQL * CF) + lags[j] * CF + (CF - 1)];
    float qin[4];
#pragma unroll
    for (int q = 0; q < 4; q++) {
        float s = lagc_b[q];
#pragma unroll
        for (int j = 0; j < 11; j++) s += lag[j] * lagc_W[q * 11 + j];
        qin[q] = tanhf(s) * PI_F;
    }
    const float* w = (r == 0) ? wx : (r == 1) ? wy : wz;
    float2 st[16];
    float f4[4];
    run_circuit(qin, w, st);
    expvals(st, r, f4);
#pragma unroll
    for (int q = 0; q < 4; q++) feats_s[bl][r * 4 + q] = f4[q];
    __syncthreads();
    float feats[12];
#pragma unroll
    for (int j = 0; j < 12; j++) feats[j] = feats_s[bl][j];
    float h[12];
#pragma unroll
    for (int i = 0; i < 12; i++) {
        float s = b1[i];
#pragma unroll
        for (int j = 0; j < 12; j++) s += feats[j] * W1[i * 12 + j];
        h[i] = fmaxf(s, 0.f);
    }
    for (int pp = 0; pp < 32; pp++) {
        int p = r * 32 + pp;
        float s = b2[p];
#pragma unroll
        for (int i = 0; i < 12; i++) s += h[i] * W2[p * 12 + i];
        d_modT[(size_t)p * NB + b] = tanhf(s);   // [p][b]: coalesced in b
    }
}

// ---------------------------------------------------------------------------
// Kernel 2: combined matrices -> fragment-order d_MT (tf32-rounded)
// ---------------------------------------------------------------------------
__global__ void prep_k(const float* __restrict__ decomp_w,
                       const float* __restrict__ trend_W, const float* __restrict__ trend_b,
                       const float* __restrict__ seas_W,  const float* __restrict__ seas_b,
                       const float* __restrict__ alpha) {
    const int c = blockIdx.x;
    const int p = blockIdx.y;
    const int j = threadIdx.x;  // 0..167
    __shared__ float ker[KW];
    __shared__ float a_sh;
    if (j == 0) {
        float mx = -1e30f;
        for (int k = 0; k < KW; k++) mx = fmaxf(mx, decomp_w[c * KW + k]);
        float sum = 0.f, e[KW];
        for (int k = 0; k < KW; k++) { e[k] = expf(decomp_w[c * KW + k] - mx); sum += e[k]; }
        for (int k = 0; k < KW; k++) ker[k] = e[k] / sum;
        a_sh = 1.f / (1.f + expf(-alpha[0]));
    }
    __syncthreads();
    const float a = a_sh;
    const float* sW = seas_W + p * SEQL;
    const float* tW = trend_W + p * SEQL;
    float sA = 0.f, sB = 0.f;
    if (j == 0) {
        for (int k = 0; k <= 12; k++) {
            float wk = ker[k];
            for (int l = 0; l <= 12 - k; l++) { sA += wk * sW[l]; sB += wk * tW[l]; }
        }
    } else if (j == SEQL - 1) {
        for (int k = 12; k < KW; k++) {
            float wk = ker[k];
            for (int l = 179 - k; l < SEQL; l++) { sA += wk * sW[l]; sB += wk * tW[l]; }
        }
    } else {
        for (int k = 0; k < KW; k++) {
            int l = j + 12 - k;
            if (l >= 0 && l < SEQL) { float wk = ker[k]; sA += wk * sW[l]; sB += wk * tW[l]; }
        }
    }
    float A = sW[j] - sA;
    float M1 = to_tf32(a * A + (1.f - a) * sB);   // n = 2p
    float M2 = to_tf32(a * A);                    // n = 2p+1
    const int kb = j >> 3, kk = j & 7, t = kk & 3, th = kk >> 2;
#pragma unroll
    for (int h = 0; h < 2; h++) {
        int n = 2 * p + h;
        int np = n >> 4, nn = n & 15, q = nn >> 3, g = nn & 7;
        int lane = g * 4 + t, reg = 2 * q + th;
        d_MT[(((size_t)c * 12 + np) * 21 + kb) * 128 + lane * 4 + reg] = h ? M2 : M1;
    }
    if (c == 0 && j == 0) {
        d_c12[p]      = a * seas_b[p] + (1.f - a) * trend_b[p];
        d_c12[NP + p] = a * seas_b[p];
    }
}

// ---------------------------------------------------------------------------
// Kernel 3: TF32 mma.sync GEMM, warp-specialized, full-K in smem.
// 576 threads: warps 0-15 consumers (4m x 4n, warp tile m32 x n48),
// warps 16-17 producers. CTA tile M=128 x N=192. 7 stages (whole K, 210KB).
// Writes d_outS[c][p][b] (coalesced sectors); reads d_modT[p][b].
// ---------------------------------------------------------------------------
#define STAGE_F4   1920                  // A 768 + B 1152 float4
#define STAGE_B    (STAGE_F4 * 16)       // 30720 bytes
#define NCHUNK     7

__global__ __launch_bounds__(576, 1) void gemm_k() {
    extern __shared__ __align__(16) float4 sm4[];
    __shared__ __align__(8) uint64_t mbar[NCHUNK];

    const int c   = blockIdx.x;
    const int b0  = blockIdx.y * 128;
    const int tid = threadIdx.x;
    const int wid  = tid >> 5;
    const int lane = tid & 31;

    const uint32_t smb = smem_u32(sm4);
    const uint32_t mbF = smem_u32(&mbar[0]);

    if (tid == 0) {
#pragma unroll
        for (int s = 0; s < NCHUNK; s++) mbar_init(mbF + 8 * s, 64);
    }
    __syncthreads();

    if (wid >= 16) {
        // ---- producer warps (2): stream the whole K into smem ----
        const int ptid = tid - 512;      // 0..63
        const float4* A4 = (const float4*)d_xT + ((size_t)c * 256 + (b0 >> 4)) * (21 * 32);
        const float4* B4 = (const float4*)d_MT + (size_t)c * 12 * (21 * 32);
        for (int kc = 0; kc < NCHUNK; kc++) {
            const int kb0 = kc * 3;
            const uint32_t D0 = smb + kc * STAGE_B;
#pragma unroll
            for (int j = 0; j < 30; j++) {
                int idx4 = j * 64 + ptid;
                const float4* src;
                if (idx4 < 768) {
                    int ba = idx4 >> 5, l4 = idx4 & 31;
                    int mbl = ba / 3, kbl = ba - mbl * 3;
                    src = A4 + ((size_t)mbl * 21 + kb0 + kbl) * 32 + l4;
                } else {
                    int j2 = idx4 - 768;
                    int bb = j2 >> 5, l4 = j2 & 31;
                    int np = bb / 3, kbl = bb - np * 3;
                    src = B4 + ((size_t)np * 21 + kb0 + kbl) * 32 + l4;
                }
                cp16(D0 + idx4 * 16, src);
            }
            cpasync_arrive(mbF + 8 * kc);
        }
    } else {
        // ---- consumer warps 0..15 : 4m x 4n ----
        const int warp_mb = (wid & 3) * 2;    // m16-blocks {0,1}+base, base 0/2/4/6
        const int warp_np = (wid >> 2) * 3;   // n16-pairs base 0/3/6/9

        float acc[2][6][4];
#pragma unroll
        for (int mi = 0; mi < 2; mi++)
#pragma unroll
            for (int ni = 0; ni < 6; ni++)
#pragma unroll
                for (int r = 0; r < 4; r++) acc[mi][ni][r] = 0.f;

        for (int kc = 0; kc < NCHUNK; kc++) {
            mbar_wait(mbF + 8 * kc, 0);
            const float4* As = sm4 + kc * STAGE_F4;
            const float4* Bs = As + 768;
#pragma unroll
            for (int kbl = 0; kbl < 3; kbl++) {
                float4 af4[2], bf4[3];
#pragma unroll
                for (int mi = 0; mi < 2; mi++)
                    af4[mi] = As[((warp_mb + mi) * 3 + kbl) * 32 + lane];
#pragma unroll
                for (int npj = 0; npj < 3; npj++)
                    bf4[npj] = Bs[((warp_np + npj) * 3 + kbl) * 32 + lane];
#pragma unroll
                for (int mi = 0; mi < 2; mi++) {
                    const uint32_t* a = (const uint32_t*)&af4[mi];
#pragma unroll
                    for (int npj = 0; npj < 3; npj++) {
                        const uint32_t* b = (const uint32_t*)&bf4[npj];
                        mma_tf32(acc[mi][npj * 2 + 0], a, b);
                        mma_tf32(acc[mi][npj * 2 + 1], a, b + 2);
                    }
                }
            }
        }

        // epilogue -> d_outS[c][p][b] (b-contiguous; full 32B sectors)
        const int gid = lane >> 2;
        const int tig = lane & 3;
        const int pbase = warp_np * 8;
        float* outc = d_outS + (size_t)c * NP * NB;
#pragma unroll
        for (int ni = 0; ni < 6; ni++) {
            const int p = pbase + ni * 4 + tig;
            const float C1 = d_c12[p];
            const float C2 = d_c12[NP + p];
            const float* modp = d_modT + (size_t)p * NB;
            float* outp = outc + (size_t)p * NB;
#pragma unroll
            for (int mi = 0; mi < 2; mi++) {
#pragma unroll
                for (int h = 0; h < 2; h++) {
                    const int b = b0 + (wid & 3) * 32 + mi * 16 + gid + h * 8;
                    const float y1 = acc[mi][ni][2 * h];
                    const float y2 = acc[mi][ni][2 * h + 1];
                    outp[b] = y1 + C1 + modp[b] * (y2 + C2);
                }
            }
        }
    }
}

// ---------------------------------------------------------------------------
// Kernel 4: d_outS[c][p][b] -> out[b][p][c]  (coalesced both sides)
// ---------------------------------------------------------------------------
__global__ __launch_bounds__(256) void outT_k(float* __restrict__ out) {
    __shared__ float tile[64][65];
    const int b0 = blockIdx.x * 64;
    const int p  = blockIdx.y;
    const int tid = threadIdx.x;
    // read: 64 c-rows x 16 float4 of b
#pragma unroll
    for (int it = 0; it < 4; it++) {
        int i = it * 256 + tid;
        int cc = i >> 4, q = i & 15;
        float4 v = *(const float4*)(d_outS + (((size_t)cc * NP + p) * NB) + b0 + q * 4);
        tile[cc][q * 4 + 0] = v.x;
        tile[cc][q * 4 + 1] = v.y;
        tile[cc][q * 4 + 2] = v.z;
        tile[cc][q * 4 + 3] = v.w;
    }
    __syncthreads();
    // write: 64 b-rows x 16 float4 of c
#pragma unroll
    for (int it = 0; it < 4; it++) {
        int i = it * 256 + tid;
        int b = i >> 4, q = i & 15;
        float4 w;
        w.x = tile[q * 4 + 0][b];
        w.y = tile[q * 4 + 1][b];
        w.z = tile[q * 4 + 2][b];
        w.w = tile[q * 4 + 3][b];
        *(float4*)(out + (size_t)(b0 + b) * (NP * CF) + (size_t)p * CF + q * 4) = w;
    }
}

// ---------------------------------------------------------------------------
extern "C" void kernel_launch(void* const* d_in, const int* in_sizes, int n_in,
                              void* d_out, int out_size) {
    const float* x        = (const float*)d_in[0];
    const float* decomp_w = (const float*)d_in[1];
    const float* trend_W  = (const float*)d_in[2];
    const float* trend_b  = (const float*)d_in[3];
    const float* seas_W   = (const float*)d_in[4];
    const float* seas_b   = (const float*)d_in[5];
    const float* lagc_W   = (const float*)d_in[6];
    const float* lagc_b   = (const float*)d_in[7];
    const float* wx       = (const float*)d_in[8];
    const float* wy       = (const float*)d_in[9];
    const float* wz       = (const float*)d_in[10];
    const float* W1       = (const float*)d_in[11];
    const float* b1       = (const float*)d_in[12];
    const float* W2       = (const float*)d_in[13];
    const float* b2       = (const float*)d_in[14];
    const float* alpha    = (const float*)d_in[15];
    float* out = (float*)d_out;

    cudaFuncSetAttribute(gemm_k, cudaFuncAttributeMaxDynamicSharedMemorySize,
                         NCHUNK * STAGE_B);

    transpose_k<<<dim3(8, 6, 128), 256>>>(x);
    mod_k<<<128, 96>>>(x, lagc_W, lagc_b, wx, wy, wz, W1, b1, W2, b2);
    prep_k<<<dim3(64, 96), 168>>>(decomp_w, trend_W, trend_b, seas_W, seas_b, alpha);
    gemm_k<<<dim3(64, 32), 576, NCHUNK * STAGE_B>>>();
    outT_k<<<dim3(64, 96), 256>>>(out);
}

// round 9
// speedup vs baseline: 2.0187x; 1.0170x over previous
#include <cuda_runtime.h>
#include <math.h>
#include <stdint.h>

#define NB    4096
#define SEQL  168
#define CF    64
#define NP    96
#define KW    25
#define PI_F  3.14159265358979f

// chunk-contiguous fragment scratch:
// d_xA: [c][kc(7)][mb(256)][kbl(3)][128]   (m16xk8 frag blocks; one CTA stage = contiguous)
// d_MB: [c][kc(7)][np(12)][kbl(3)][128]    (n16xk8 frag blocks)
__device__ float d_xA[(size_t)CF * 7 * 256 * 3 * 128];
__device__ float d_MB[(size_t)CF * 7 * 12 * 3 * 128];
__device__ float d_modT[(size_t)NP * NB];            // [p][b]
__device__ float d_outS[(size_t)CF * NP * NB];       // [c][p][b] gemm scratch
__device__ float d_c12[2 * NP];

__device__ __forceinline__ float to_tf32(float f) {
    uint32_t u;
    asm("cvt.rna.tf32.f32 %0, %1;" : "=r"(u) : "f"(f));
    return __uint_as_float(u);
}
__device__ __forceinline__ uint32_t smem_u32(const void* p) {
    uint32_t a;
    asm("{ .reg .u64 t; cvta.to.shared.u64 t, %1; cvt.u32.u64 %0, t; }" : "=r"(a) : "l"(p));
    return a;
}
__device__ __forceinline__ void mma_tf32(float* d, const uint32_t* a, const uint32_t* b) {
    asm volatile(
        "mma.sync.aligned.m16n8k8.row.col.f32.tf32.tf32.f32 "
        "{%0,%1,%2,%3}, {%4,%5,%6,%7}, {%8,%9}, {%0,%1,%2,%3};"
        : "+f"(d[0]), "+f"(d[1]), "+f"(d[2]), "+f"(d[3])
        : "r"(a[0]), "r"(a[1]), "r"(a[2]), "r"(a[3]), "r"(b[0]), "r"(b[1]));
}
__device__ __forceinline__ void mbar_init(uint32_t a, uint32_t cnt) {
    asm volatile("mbarrier.init.shared.b64 [%0], %1;" :: "r"(a), "r"(cnt) : "memory");
}
__device__ __forceinline__ void mbar_expect_tx(uint32_t a, uint32_t bytes) {
    asm volatile("mbarrier.arrive.expect_tx.shared.b64 _, [%0], %1;"
                 :: "r"(a), "r"(bytes) : "memory");
}
__device__ __forceinline__ void mbar_wait(uint32_t a, uint32_t parity) {
    asm volatile(
        "{\n\t.reg .pred P;\n\t"
        "WL_%=:\n\t"
        "mbarrier.try_wait.parity.acquire.cta.shared::cta.b64 P, [%0], %1, 0x989680;\n\t"
        "@!P bra WL_%=;\n\t}"
        :: "r"(a), "r"(parity) : "memory");
}
__device__ __forceinline__ void tma_bulk(uint32_t dst, const void* src, uint32_t bytes,
                                         uint32_t mbar) {
    asm volatile(
        "cp.async.bulk.shared::cta.global.mbarrier::complete_tx::bytes [%0], [%1], %2, [%3];"
        :: "r"(dst), "l"(src), "r"(bytes), "r"(mbar) : "memory");
}

// ---------------------------------------------------------------------------
// Kernel 0: transpose x[b][l][c] -> chunk-contiguous fragment d_xA (tf32)
// ---------------------------------------------------------------------------
__global__ __launch_bounds__(256) void transpose_k(const float* __restrict__ x) {
    __shared__ float sh[8][32][33];     // [c][k][b]
    const int c0 = blockIdx.x * 8;
    const int l0 = blockIdx.y * 32;
    const int b0 = blockIdx.z * 32;
    const int tid = threadIdx.x;
    const float4* x4 = (const float4*)x;
#pragma unroll
    for (int it = 0; it < 8; it++) {
        int i = it * 256 + tid;
        int c4i = i & 1, l = (i >> 1) & 31, b = i >> 6;
        int lg = l0 + l;
        float4 v = make_float4(0.f, 0.f, 0.f, 0.f);
        if (lg < SEQL)
            v = x4[(size_t)(b0 + b) * (SEQL * 16) + (size_t)lg * 16 + (c0 >> 2) + c4i];
        sh[c4i * 4 + 0][l][b] = to_tf32(v.x);
        sh[c4i * 4 + 1][l][b] = to_tf32(v.y);
        sh[c4i * 4 + 2][l][b] = to_tf32(v.z);
        sh[c4i * 4 + 3][l][b] = to_tf32(v.w);
    }
    __syncthreads();
    float4* o4 = (float4*)d_xA;
#pragma unroll
    for (int it = 0; it < 8; it++) {
        int i = it * 256 + tid;
        int lane = i & 31, kbl = (i >> 5) & 3, mbl = (i >> 7) & 1, cl = i >> 8;
        int kb_g = (l0 >> 3) + kbl;
        if (kb_g >= 21) continue;
        int kc = kb_g / 3, kr = kb_g - kc * 3;
        int g = lane >> 2, t = lane & 3;
        float4 w;
        w.x = sh[cl][kbl * 8 + t]    [mbl * 16 + g];
        w.y = sh[cl][kbl * 8 + t]    [mbl * 16 + g + 8];
        w.z = sh[cl][kbl * 8 + t + 4][mbl * 16 + g];
        w.w = sh[cl][kbl * 8 + t + 4][mbl * 16 + g + 8];
        size_t idx4 = ((((size_t)(c0 + cl) * 7 + kc) * 256 + (b0 >> 4) + mbl) * 3 + kr) * 32 + lane;
        o4[idx4] = w;
    }
}

// ---------------------------------------------------------------------------
// Kernel 1: per-batch quantum path -> d_modT[p][b]
// ---------------------------------------------------------------------------
__device__ __forceinline__ float2 cmulf(float2 a, float2 b) {
    return make_float2(a.x * b.x - a.y * b.y, a.x * b.y + a.y * b.x);
}

__device__ void run_circuit(const float qin[4], const float* __restrict__ w, float2 s[16]) {
#pragma unroll
    for (int i = 0; i < 16; i++) s[i] = make_float2(0.f, 0.f);
    s[0].x = 1.f;
#pragma unroll
    for (int l = 0; l < 3; l++) {
#pragma unroll
        for (int q = 0; q < 4; q++) {
            const int m = 8 >> q;
            float sn, cs; sincosf(0.5f * qin[q], &sn, &cs);
#pragma unroll
            for (int i = 0; i < 16; i++) {
                if ((i & m) == 0) {
                    float2 a0 = s[i], a1 = s[i | m];
                    s[i]     = make_float2(cs * a0.x - sn * a1.x, cs * a0.y - sn * a1.y);
                    s[i | m] = make_float2(sn * a0.x + cs * a1.x, sn * a0.y + cs * a1.y);
                }
            }
        }
#pragma unroll
        for (int q = 0; q < 4; q++) {
            const int m = 8 >> q;
            float phi = w[(l * 4 + q) * 3 + 0];
            float th  = w[(l * 4 + q) * 3 + 1];
            float om  = w[(l * 4 + q) * 3 + 2];
            float st, ct; sincosf(0.5f * th, &st, &ct);
            float s1, c1; sincosf(-0.5f * (phi + om), &s1, &c1);
            float s2, c2; sincosf( 0.5f * (phi - om), &s2, &c2);
            float2 U00 = make_float2( c1 * ct,  s1 * ct);
            float2 U01 = make_float2(-c2 * st, -s2 * st);
            float2 U10 = make_float2( c2 * st, -s2 * st);
            float2 U11 = make_float2( c1 * ct, -s1 * ct);
#pragma unroll
            for (int i = 0; i < 16; i++) {
                if ((i & m) == 0) {
                    float2 a0 = s[i], a1 = s[i | m];
                    float2 n0 = cmulf(U00, a0); float2 t = cmulf(U01, a1);
                    n0.x += t.x; n0.y += t.y;
                    float2 n1 = cmulf(U10, a0); t = cmulf(U11, a1);
                    n1.x += t.x; n1.y += t.y;
                    s[i] = n0; s[i | m] = n1;
                }
            }
        }
#pragma unroll
        for (int q = 0; q < 4; q++) {
            const int cm = 8 >> q;
            const int tm = 8 >> ((q + 1) & 3);
#pragma unroll
            for (int i = 0; i < 16; i++) {
                if ((i & cm) && !(i & tm)) {
                    float2 t = s[i]; s[i] = s[i | tm]; s[i | tm] = t;
                }
            }
        }
    }
}

__device__ __forceinline__ void expvals(const float2 s[16], int pauli, float* o) {
#pragma unroll
    for (int q = 0; q < 4; q++) {
        const int m = 8 >> q;
        float acc = 0.f;
#pragma unroll
        for (int i = 0; i < 16; i++) {
            if ((i & m) == 0) {
                float2 a0 = s[i], a1 = s[i | m];
                if (pauli == 0)      acc += a0.x * a1.x + a0.y * a1.y;
                else if (pauli == 1) acc += a0.x * a1.y - a0.y * a1.x;
                else                 acc += a0.x * a0.x + a0.y * a0.y
                                          - a1.x * a1.x - a1.y * a1.y;
            }
        }
        o[q] = (pauli == 2) ? acc : 2.f * acc;
    }
}

__global__ __launch_bounds__(96) void mod_k(const float* __restrict__ x,
                      const float* __restrict__ lagc_W, const float* __restrict__ lagc_b,
                      const float* __restrict__ wx, const float* __restrict__ wy,
                      const float* __restrict__ wz,
                      const float* __restrict__ W1, const float* __restrict__ b1,
                      const float* __restrict__ W2, const float* __restrict__ b2) {
    __shared__ float feats_s[32][13];
    const int bl = threadIdx.x & 31;
    const int r  = threadIdx.x >> 5;
    const int b  = blockIdx.x * 32 + bl;
    const int lags[11] = {167, 166, 165, 164, 163, 162, 145, 144, 143, 1, 0};
    float lag[11];
#pragma unroll
    for (int j = 0; j < 11; j++)
        lag[j] = x[(size_t)b * (SEQL * CF) + lags[j] * CF + (CF - 1)];
    float qin[4];
#pragma unroll
    for (int q = 0; q < 4; q++) {
        float s = lagc_b[q];
#pragma unroll
        for (int j = 0; j < 11; j++) s += lag[j] * lagc_W[q * 11 + j];
        qin[q] = tanhf(s) * PI_F;
    }
    const float* w = (r == 0) ? wx : (r == 1) ? wy : wz;
    float2 st[16];
    float f4[4];
    run_circuit(qin, w, st);
    expvals(st, r, f4);
#pragma unroll
    for (int q = 0; q < 4; q++) feats_s[bl][r * 4 + q] = f4[q];
    __syncthreads();
    float feats[12];
#pragma unroll
    for (int j = 0; j < 12; j++) feats[j] = feats_s[bl][j];
    float h[12];
#pragma unroll
    for (int i = 0; i < 12; i++) {
        float s = b1[i];
#pragma unroll
        for (int j = 0; j < 12; j++) s += feats[j] * W1[i * 12 + j];
        h[i] = fmaxf(s, 0.f);
    }
    for (int pp = 0; pp < 32; pp++) {
        int p = r * 32 + pp;
        float s = b2[p];
#pragma unroll
        for (int i = 0; i < 12; i++) s += h[i] * W2[p * 12 + i];
        d_modT[(size_t)p * NB + b] = tanhf(s);
    }
}

// ---------------------------------------------------------------------------
// Kernel 2: combined matrices -> chunk-contiguous fragment d_MB (tf32)
// ---------------------------------------------------------------------------
__global__ void prep_k(const float* __restrict__ decomp_w,
                       const float* __restrict__ trend_W, const float* __restrict__ trend_b,
                       const float* __restrict__ seas_W,  const float* __restrict__ seas_b,
                       const float* __restrict__ alpha) {
    const int c = blockIdx.x;
    const int p = blockIdx.y;
    const int j = threadIdx.x;  // 0..167
    __shared__ float ker[KW];
    __shared__ float a_sh;
    if (j == 0) {
        float mx = -1e30f;
        for (int k = 0; k < KW; k++) mx = fmaxf(mx, decomp_w[c * KW + k]);
        float sum = 0.f, e[KW];
        for (int k = 0; k < KW; k++) { e[k] = expf(decomp_w[c * KW + k] - mx); sum += e[k]; }
        for (int k = 0; k < KW; k++) ker[k] = e[k] / sum;
        a_sh = 1.f / (1.f + expf(-alpha[0]));
    }
    __syncthreads();
    const float a = a_sh;
    const float* sW = seas_W + p * SEQL;
    const float* tW = trend_W + p * SEQL;
    float sA = 0.f, sB = 0.f;
    if (j == 0) {
        for (int k = 0; k <= 12; k++) {
            float wk = ker[k];
            for (int l = 0; l <= 12 - k; l++) { sA += wk * sW[l]; sB += wk * tW[l]; }
        }
    } else if (j == SEQL - 1) {
        for (int k = 12; k < KW; k++) {
            float wk = ker[k];
            for (int l = 179 - k; l < SEQL; l++) { sA += wk * sW[l]; sB += wk * tW[l]; }
        }
    } else {
        for (int k = 0; k < KW; k++) {
            int l = j + 12 - k;
            if (l >= 0 && l < SEQL) { float wk = ker[k]; sA += wk * sW[l]; sB += wk * tW[l]; }
        }
    }
    float A = sW[j] - sA;
    float M1 = to_tf32(a * A + (1.f - a) * sB);   // n = 2p
    float M2 = to_tf32(a * A);                    // n = 2p+1
    const int kb = j >> 3, kk = j & 7, t = kk & 3, th = kk >> 2;
    const int kc = kb / 3, kr = kb - kc * 3;
#pragma unroll
    for (int h = 0; h < 2; h++) {
        int n = 2 * p + h;
        int np = n >> 4, nn = n & 15, q = nn >> 3, g = nn & 7;
        int lane = g * 4 + t, reg = 2 * q + th;
        d_MB[((((size_t)c * 7 + kc) * 12 + np) * 3 + kr) * 128 + lane * 4 + reg] = h ? M2 : M1;
    }
    if (c == 0 && j == 0) {
        d_c12[p]      = a * seas_b[p] + (1.f - a) * trend_b[p];
        d_c12[NP + p] = a * seas_b[p];
    }
}

// ---------------------------------------------------------------------------
// Kernel 3: TF32 mma.sync GEMM; bulk-TMA fills whole K (7 stages, 215KB).
// 512 threads = 16 consumer warps (4m x 4n, warp tile m32 x n48).
// Thread 0 issues 7 x (expect_tx + 2 cp.async.bulk) upfront.
// ---------------------------------------------------------------------------
#define STAGE_F4   1920                  // A 768 + B 1152 float4
#define STAGE_B    (STAGE_F4 * 16)       // 30720 bytes
#define A_BYTES    12288
#define B_BYTES    18432
#define NCHUNK     7

__global__ __launch_bounds__(512, 1) void gemm_k() {
    extern __shared__ __align__(16) float4 sm4[];
    __shared__ __align__(8) uint64_t mbar[NCHUNK];

    const int c   = blockIdx.x;
    const int b0  = blockIdx.y * 128;
    const int tid = threadIdx.x;
    const int wid  = tid >> 5;
    const int lane = tid & 31;

    const uint32_t smb = smem_u32(sm4);
    const uint32_t mbF = smem_u32(&mbar[0]);

    if (tid == 0) {
#pragma unroll
        for (int s = 0; s < NCHUNK; s++) mbar_init(mbF + 8 * s, 1);
    }
    __syncthreads();

    if (tid == 0) {
#pragma unroll
        for (int kc = 0; kc < NCHUNK; kc++) {
            const uint32_t D0 = smb + kc * STAGE_B;
            const float* srcA = d_xA + (((size_t)c * 7 + kc) * 256 + (b0 >> 4)) * 384;
            const float* srcB = d_MB + (((size_t)c * 7 + kc) * 12) * 384;
            mbar_expect_tx(mbF + 8 * kc, STAGE_B);
            tma_bulk(D0, srcA, A_BYTES, mbF + 8 * kc);
            tma_bulk(D0 + A_BYTES, srcB, B_BYTES, mbF + 8 * kc);
        }
    }

    // ---- all 16 warps consume ----
    const int warp_mb = (wid & 3) * 2;    // m16-block base 0/2/4/6
    const int warp_np = (wid >> 2) * 3;   // n16-pair base 0/3/6/9

    float acc[2][6][4];
#pragma unroll
    for (int mi = 0; mi < 2; mi++)
#pragma unroll
        for (int ni = 0; ni < 6; ni++)
#pragma unroll
            for (int r = 0; r < 4; r++) acc[mi][ni][r] = 0.f;

    for (int kc = 0; kc < NCHUNK; kc++) {
        mbar_wait(mbF + 8 * kc, 0);
        const float4* As = sm4 + kc * STAGE_F4;
        const float4* Bs = As + 768;
#pragma unroll
        for (int kbl = 0; kbl < 3; kbl++) {
            float4 af4[2], bf4[3];
#pragma unroll
            for (int mi = 0; mi < 2; mi++)
                af4[mi] = As[((warp_mb + mi) * 3 + kbl) * 32 + lane];
#pragma unroll
            for (int npj = 0; npj < 3; npj++)
                bf4[npj] = Bs[((warp_np + npj) * 3 + kbl) * 32 + lane];
#pragma unroll
            for (int mi = 0; mi < 2; mi++) {
                const uint32_t* a = (const uint32_t*)&af4[mi];
#pragma unroll
                for (int npj = 0; npj < 3; npj++) {
                    const uint32_t* b = (const uint32_t*)&bf4[npj];
                    mma_tf32(acc[mi][npj * 2 + 0], a, b);
                    mma_tf32(acc[mi][npj * 2 + 1], a, b + 2);
                }
            }
        }
    }

    // epilogue -> d_outS[c][p][b]
    const int gid = lane >> 2;
    const int tig = lane & 3;
    const int pbase = warp_np * 8;
    float* outc = d_outS + (size_t)c * NP * NB;
#pragma unroll
    for (int ni = 0; ni < 6; ni++) {
        const int p = pbase + ni * 4 + tig;
        const float C1 = d_c12[p];
        const float C2 = d_c12[NP + p];
        const float* modp = d_modT + (size_t)p * NB;
        float* outp = outc + (size_t)p * NB;
#pragma unroll
        for (int mi = 0; mi < 2; mi++) {
#pragma unroll
            for (int h = 0; h < 2; h++) {
                const int b = b0 + (wid & 3) * 32 + mi * 16 + gid + h * 8;
                const float y1 = acc[mi][ni][2 * h];
                const float y2 = acc[mi][ni][2 * h + 1];
                outp[b] = y1 + C1 + modp[b] * (y2 + C2);
            }
        }
    }
}

// ---------------------------------------------------------------------------
// Kernel 4: d_outS[c][p][b] -> out[b][p][c]  (coalesced both sides)
// ---------------------------------------------------------------------------
__global__ __launch_bounds__(256) void outT_k(float* __restrict__ out) {
    __shared__ float tile[64][65];
    const int b0 = blockIdx.x * 64;
    const int p  = blockIdx.y;
    const int tid = threadIdx.x;
#pragma unroll
    for (int it = 0; it < 4; it++) {
        int i = it * 256 + tid;
        int cc = i >> 4, q = i & 15;
        float4 v = *(const float4*)(d_outS + (((size_t)cc * NP + p) * NB) + b0 + q * 4);
        tile[cc][q * 4 + 0] = v.x;
        tile[cc][q * 4 + 1] = v.y;
        tile[cc][q * 4 + 2] = v.z;
        tile[cc][q * 4 + 3] = v.w;
    }
    __syncthreads();
#pragma unroll
    for (int it = 0; it < 4; it++) {
        int i = it * 256 + tid;
        int b = i >> 4, q = i & 15;
        float4 w;
        w.x = tile[q * 4 + 0][b];
        w.y = tile[q * 4 + 1][b];
        w.z = tile[q * 4 + 2][b];
        w.w = tile[q * 4 + 3][b];
        *(float4*)(out + (size_t)(b0 + b) * (NP * CF) + (size_t)p * CF + q * 4) = w;
    }
}

// ---------------------------------------------------------------------------
extern "C" void kernel_launch(void* const* d_in, const int* in_sizes, int n_in,
                              void* d_out, int out_size) {
    const float* x        = (const float*)d_in[0];
    const float* decomp_w = (const float*)d_in[1];
    const float* trend_W  = (const float*)d_in[2];
    const float* trend_b  = (const float*)d_in[3];
    const float* seas_W   = (const float*)d_in[4];
    const float* seas_b   = (const float*)d_in[5];
    const float* lagc_W   = (const float*)d_in[6];
    const float* lagc_b   = (const float*)d_in[7];
    const float* wx       = (const float*)d_in[8];
    const float* wy       = (const float*)d_in[9];
    const float* wz       = (const float*)d_in[10];
    const float* W1       = (const float*)d_in[11];
    const float* b1       = (const float*)d_in[12];
    const float* W2       = (const float*)d_in[13];
    const float* b2       = (const float*)d_in[14];
    const float* alpha    = (const float*)d_in[15];
    float* out = (float*)d_out;

    cudaFuncSetAttribute(gemm_k, cudaFuncAttributeMaxDynamicSharedMemorySize,
                         NCHUNK * STAGE_B);

    transpose_k<<<dim3(8, 6, 128), 256>>>(x);
    mod_k<<<128, 96>>>(x, lagc_W, lagc_b, wx, wy, wz, W1, b1, W2, b2);
    prep_k<<<dim3(64, 96), 168>>>(decomp_w, trend_W, trend_b, seas_W, seas_b, alpha);
    gemm_k<<<dim3(64, 32), 512, NCHUNK * STAGE_B>>>();
    outT_k<<<dim3(64, 96), 256>>>(out);
}

// round 11
// speedup vs baseline: 2.1782x; 1.0790x over previous
#include <cuda_runtime.h>
#include <math.h>
#include <stdint.h>

#define NB    4096
#define SEQL  168
#define CF    64
#define NP    96
#define KW    25
#define PI_F  3.14159265358979f

// chunk-contiguous fragment scratch:
// d_xA: [c][kc(7)][mb(256)][kbl(3)][128]   (m16xk8 frag blocks; one CTA stage = contiguous)
// d_MB: [c][kc(7)][np(12)][kbl(3)][128]    (n16xk8 frag blocks)
__device__ float d_xA[(size_t)CF * 7 * 256 * 3 * 128];
__device__ float d_MB[(size_t)CF * 7 * 12 * 3 * 128];
__device__ float d_modT[(size_t)NP * NB];            // [p][b]
__device__ float d_outS[(size_t)CF * NP * NB];       // [c][p][b] gemm scratch
__device__ float d_c12[2 * NP];

__device__ __forceinline__ float to_tf32(float f) {
    uint32_t u;
    asm("cvt.rna.tf32.f32 %0, %1;" : "=r"(u) : "f"(f));
    return __uint_as_float(u);
}
__device__ __forceinline__ uint32_t smem_u32(const void* p) {
    uint32_t a;
    asm("{ .reg .u64 t; cvta.to.shared.u64 t, %1; cvt.u32.u64 %0, t; }" : "=r"(a) : "l"(p));
    return a;
}
__device__ __forceinline__ void mma_tf32(float* d, const uint32_t* a, const uint32_t* b) {
    asm volatile(
        "mma.sync.aligned.m16n8k8.row.col.f32.tf32.tf32.f32 "
        "{%0,%1,%2,%3}, {%4,%5,%6,%7}, {%8,%9}, {%0,%1,%2,%3};"
        : "+f"(d[0]), "+f"(d[1]), "+f"(d[2]), "+f"(d[3])
        : "r"(a[0]), "r"(a[1]), "r"(a[2]), "r"(a[3]), "r"(b[0]), "r"(b[1]));
}
__device__ __forceinline__ void mbar_init(uint32_t a, uint32_t cnt) {
    asm volatile("mbarrier.init.shared.b64 [%0], %1;" :: "r"(a), "r"(cnt) : "memory");
}
__device__ __forceinline__ void mbar_expect_tx(uint32_t a, uint32_t bytes) {
    asm volatile("mbarrier.arrive.expect_tx.shared.b64 _, [%0], %1;"
                 :: "r"(a), "r"(bytes) : "memory");
}
__device__ __forceinline__ void mbar_wait(uint32_t a, uint32_t parity) {
    asm volatile(
        "{\n\t.reg .pred P;\n\t"
        "WL_%=:\n\t"
        "mbarrier.try_wait.parity.acquire.cta.shared::cta.b64 P, [%0], %1, 0x989680;\n\t"
        "@!P bra WL_%=;\n\t}"
        :: "r"(a), "r"(parity) : "memory");
}
__device__ __forceinline__ void tma_bulk(uint32_t dst, const void* src, uint32_t bytes,
                                         uint32_t mbar) {
    asm volatile(
        "cp.async.bulk.shared::cta.global.mbarrier::complete_tx::bytes [%0], [%1], %2, [%3];"
        :: "r"(dst), "l"(src), "r"(bytes), "r"(mbar) : "memory");
}

// ---------------------------------------------------------------------------
// quantum helpers
// ---------------------------------------------------------------------------
__device__ __forceinline__ float2 cmulf(float2 a, float2 b) {
    return make_float2(a.x * b.x - a.y * b.y, a.x * b.y + a.y * b.x);
}

__device__ void run_circuit(const float qin[4], const float* __restrict__ w, float2 s[16]) {
#pragma unroll
    for (int i = 0; i < 16; i++) s[i] = make_float2(0.f, 0.f);
    s[0].x = 1.f;
#pragma unroll
    for (int l = 0; l < 3; l++) {
#pragma unroll
        for (int q = 0; q < 4; q++) {
            const int m = 8 >> q;
            float sn, cs; sincosf(0.5f * qin[q], &sn, &cs);
#pragma unroll
            for (int i = 0; i < 16; i++) {
                if ((i & m) == 0) {
                    float2 a0 = s[i], a1 = s[i | m];
                    s[i]     = make_float2(cs * a0.x - sn * a1.x, cs * a0.y - sn * a1.y);
                    s[i | m] = make_float2(sn * a0.x + cs * a1.x, sn * a0.y + cs * a1.y);
                }
            }
        }
#pragma unroll
        for (int q = 0; q < 4; q++) {
            const int m = 8 >> q;
            float phi = w[(l * 4 + q) * 3 + 0];
            float th  = w[(l * 4 + q) * 3 + 1];
            float om  = w[(l * 4 + q) * 3 + 2];
            float st, ct; sincosf(0.5f * th, &st, &ct);
            float s1, c1; sincosf(-0.5f * (phi + om), &s1, &c1);
            float s2, c2; sincosf( 0.5f * (phi - om), &s2, &c2);
            float2 U00 = make_float2( c1 * ct,  s1 * ct);
            float2 U01 = make_float2(-c2 * st, -s2 * st);
            float2 U10 = make_float2( c2 * st, -s2 * st);
            float2 U11 = make_float2( c1 * ct, -s1 * ct);
#pragma unroll
            for (int i = 0; i < 16; i++) {
                if ((i & m) == 0) {
                    float2 a0 = s[i], a1 = s[i | m];
                    float2 n0 = cmulf(U00, a0); float2 t = cmulf(U01, a1);
                    n0.x += t.x; n0.y += t.y;
                    float2 n1 = cmulf(U10, a0); t = cmulf(U11, a1);
                    n1.x += t.x; n1.y += t.y;
                    s[i] = n0; s[i | m] = n1;
                }
            }
        }
#pragma unroll
        for (int q = 0; q < 4; q++) {
            const int cm = 8 >> q;
            const int tm = 8 >> ((q + 1) & 3);
#pragma unroll
            for (int i = 0; i < 16; i++) {
                if ((i & cm) && !(i & tm)) {
                    float2 t = s[i]; s[i] = s[i | tm]; s[i | tm] = t;
                }
            }
        }
    }
}

__device__ __forceinline__ void expvals(const float2 s[16], int pauli, float* o) {
#pragma unroll
    for (int q = 0; q < 4; q++) {
        const int m = 8 >> q;
        float acc = 0.f;
#pragma unroll
        for (int i = 0; i < 16; i++) {
            if ((i & m) == 0) {
                float2 a0 = s[i], a1 = s[i | m];
                if (pauli == 0)      acc += a0.x * a1.x + a0.y * a1.y;
                else if (pauli == 1) acc += a0.x * a1.y - a0.y * a1.x;
                else                 acc += a0.x * a0.x + a0.y * a0.y
                                          - a1.x * a1.x - a1.y * a1.y;
            }
        }
        o[q] = (pauli == 2) ? acc : 2.f * acc;
    }
}

// ---------------------------------------------------------------------------
// Kernel 0 (fused pre-work): heterogeneous blocks.
//   bid <  128           : mod   (96 active threads)  -> d_modT
//   128 <= bid < 6272    : prep  (168 active threads) -> d_MB, d_c12
//   bid >= 6272          : transpose (256 threads)    -> d_xA
// mod/prep first so they overlap the memory-bound transpose blocks.
// ---------------------------------------------------------------------------
#define N_MOD   128
#define N_PREP  6144
#define N_TR    6144

__global__ __launch_bounds__(256) void pre_k(const float* __restrict__ x,
                      const float* __restrict__ decomp_w,
                      const float* __restrict__ trend_W, const float* __restrict__ trend_b,
                      const float* __restrict__ seas_W,  const float* __restrict__ seas_b,
                      const float* __restrict__ lagc_W,  const float* __restrict__ lagc_b,
                      const float* __restrict__ wx, const float* __restrict__ wy,
                      const float* __restrict__ wz,
                      const float* __restrict__ W1, const float* __restrict__ b1,
                      const float* __restrict__ W2, const float* __restrict__ b2,
                      const float* __restrict__ alpha) {
    __shared__ float sh_raw[8 * 32 * 33];      // 33.8KB, shared by all paths
    const int bid = blockIdx.x;
    const int tid = threadIdx.x;

    if (bid < N_MOD) {
        // ================= mod path =================
        float (*feats_s)[13] = (float (*)[13])sh_raw;
        const int bl = tid & 31;
        const int r  = tid >> 5;
        const bool act = tid < 96;
        const int b  = bid * 32 + bl;
        float h[12];
        if (act) {
            const int lags[11] = {167, 166, 165, 164, 163, 162, 145, 144, 143, 1, 0};
            float lag[11];
#pragma unroll
            for (int j = 0; j < 11; j++)
                lag[j] = x[(size_t)b * (SEQL * CF) + lags[j] * CF + (CF - 1)];
            float qin[4];
#pragma unroll
            for (int q = 0; q < 4; q++) {
                float s = lagc_b[q];
#pragma unroll
                for (int j = 0; j < 11; j++) s += lag[j] * lagc_W[q * 11 + j];
                qin[q] = tanhf(s) * PI_F;
            }
            const float* w = (r == 0) ? wx : (r == 1) ? wy : wz;
            float2 st[16];
            float f4[4];
            run_circuit(qin, w, st);
            expvals(st, r, f4);
#pragma unroll
            for (int q = 0; q < 4; q++) feats_s[bl][r * 4 + q] = f4[q];
        }
        __syncthreads();
        if (act) {
            float feats[12];
#pragma unroll
            for (int j = 0; j < 12; j++) feats[j] = feats_s[bl][j];
#pragma unroll
            for (int i = 0; i < 12; i++) {
                float s = b1[i];
#pragma unroll
                for (int j = 0; j < 12; j++) s += feats[j] * W1[i * 12 + j];
                h[i] = fmaxf(s, 0.f);
            }
            for (int pp = 0; pp < 32; pp++) {
                int p = r * 32 + pp;
                float s = b2[p];
#pragma unroll
                for (int i = 0; i < 12; i++) s += h[i] * W2[p * 12 + i];
                d_modT[(size_t)p * NB + b] = tanhf(s);
            }
        }
    } else if (bid < N_MOD + N_PREP) {
        // ================= prep path =================
        const int pp = bid - N_MOD;
        const int c = pp & 63;
        const int p = pp >> 6;
        const int j = tid;
        float* ker = sh_raw;
        float* a_sh = sh_raw + KW;
        if (j == 0) {
            float mx = -1e30f;
            for (int k = 0; k < KW; k++) mx = fmaxf(mx, decomp_w[c * KW + k]);
            float sum = 0.f, e[KW];
            for (int k = 0; k < KW; k++) { e[k] = expf(decomp_w[c * KW + k] - mx); sum += e[k]; }
            for (int k = 0; k < KW; k++) ker[k] = e[k] / sum;
            a_sh[0] = 1.f / (1.f + expf(-alpha[0]));
        }
        __syncthreads();
        if (j < SEQL) {
            const float a = a_sh[0];
            const float* sW = seas_W + p * SEQL;
            const float* tW = trend_W + p * SEQL;
            float sA = 0.f, sB = 0.f;
            if (j == 0) {
                for (int k = 0; k <= 12; k++) {
                    float wk = ker[k];
                    for (int l = 0; l <= 12 - k; l++) { sA += wk * sW[l]; sB += wk * tW[l]; }
                }
            } else if (j == SEQL - 1) {
                for (int k = 12; k < KW; k++) {
                    float wk = ker[k];
                    for (int l = 179 - k; l < SEQL; l++) { sA += wk * sW[l]; sB += wk * tW[l]; }
                }
            } else {
                for (int k = 0; k < KW; k++) {
                    int l = j + 12 - k;
                    if (l >= 0 && l < SEQL) { float wk = ker[k]; sA += wk * sW[l]; sB += wk * tW[l]; }
                }
            }
            float A = sW[j] - sA;
            float M1 = to_tf32(a * A + (1.f - a) * sB);   // n = 2p
            float M2 = to_tf32(a * A);                    // n = 2p+1
            const int kb = j >> 3, kk = j & 7, t = kk & 3, th = kk >> 2;
            const int kc = kb / 3, kr = kb - kc * 3;
#pragma unroll
            for (int h2 = 0; h2 < 2; h2++) {
                int n = 2 * p + h2;
                int np = n >> 4, nn = n & 15, q = nn >> 3, g = nn & 7;
                int lane = g * 4 + t, reg = 2 * q + th;
                d_MB[((((size_t)c * 7 + kc) * 12 + np) * 3 + kr) * 128 + lane * 4 + reg]
                    = h2 ? M2 : M1;
            }
            if (c == 0 && j == 0) {
                d_c12[p]      = a * seas_b[p] + (1.f - a) * trend_b[p];
                d_c12[NP + p] = a * seas_b[p];
            }
        }
    } else {
        // ================= transpose path =================
        float (*sh)[32][33] = (float (*)[32][33])sh_raw;
        const int t  = bid - (N_MOD + N_PREP);
        const int c0 = (t & 7) * 8;
        const int l0 = ((t >> 3) % 6) * 32;
        const int b0 = (t / 48) * 32;
        const float4* x4 = (const float4*)x;
#pragma unroll
        for (int it = 0; it < 8; it++) {
            int i = it * 256 + tid;
            int c4i = i & 1, l = (i >> 1) & 31, b = i >> 6;
            int lg = l0 + l;
            float4 v = make_float4(0.f, 0.f, 0.f, 0.f);
            if (lg < SEQL)
                v = x4[(size_t)(b0 + b) * (SEQL * 16) + (size_t)lg * 16 + (c0 >> 2) + c4i];
            sh[c4i * 4 + 0][l][b] = to_tf32(v.x);
            sh[c4i * 4 + 1][l][b] = to_tf32(v.y);
            sh[c4i * 4 + 2][l][b] = to_tf32(v.z);
            sh[c4i * 4 + 3][l][b] = to_tf32(v.w);
        }
        __syncthreads();
        float4* o4 = (float4*)d_xA;
#pragma unroll
        for (int it = 0; it < 8; it++) {
            int i = it * 256 + tid;
            int lane = i & 31, kbl = (i >> 5) & 3, mbl = (i >> 7) & 1, cl = i >> 8;
            int kb_g = (l0 >> 3) + kbl;
            if (kb_g >= 21) continue;
            int kc = kb_g / 3, kr = kb_g - kc * 3;
            int g = lane >> 2, tg = lane & 3;
            float4 w;
            w.x = sh[cl][kbl * 8 + tg]    [mbl * 16 + g];
            w.y = sh[cl][kbl * 8 + tg]    [mbl * 16 + g + 8];
            w.z = sh[cl][kbl * 8 + tg + 4][mbl * 16 + g];
            w.w = sh[cl][kbl * 8 + tg + 4][mbl * 16 + g + 8];
            size_t idx4 = ((((size_t)(c0 + cl) * 7 + kc) * 256 + (b0 >> 4) + mbl) * 3 + kr) * 32
                        + lane;
            o4[idx4] = w;
        }
    }
}

// ---------------------------------------------------------------------------
// Kernel 1: TF32 mma.sync GEMM; bulk-TMA fills whole K (7 stages, 215KB).
// 512 threads = 16 consumer warps (4m x 4n, warp tile m32 x n48).
// ---------------------------------------------------------------------------
#define STAGE_F4   1920                  // A 768 + B 1152 float4
#define STAGE_B    (STAGE_F4 * 16)       // 30720 bytes
#define A_BYTES    12288
#define B_BYTES    18432
#define NCHUNK     7

__global__ __launch_bounds__(512, 1) void gemm_k() {
    extern __shared__ __align__(16) float4 sm4[];
    __shared__ __align__(8) uint64_t mbar[NCHUNK];

    const int c   = blockIdx.x;
    const int b0  = blockIdx.y * 128;
    const int tid = threadIdx.x;
    const int wid  = tid >> 5;
    const int lane = tid & 31;

    const uint32_t smb = smem_u32(sm4);
    const uint32_t mbF = smem_u32(&mbar[0]);

    if (tid == 0) {
#pragma unroll
        for (int s = 0; s < NCHUNK; s++) mbar_init(mbF + 8 * s, 1);
    }
    __syncthreads();

    if (tid == 0) {
#pragma unroll
        for (int kc = 0; kc < NCHUNK; kc++) {
            const uint32_t D0 = smb + kc * STAGE_B;
            const float* srcA = d_xA + (((size_t)c * 7 + kc) * 256 + (b0 >> 4)) * 384;
            const float* srcB = d_MB + (((size_t)c * 7 + kc) * 12) * 384;
            mbar_expect_tx(mbF + 8 * kc, STAGE_B);
            tma_bulk(D0, srcA, A_BYTES, mbF + 8 * kc);
            tma_bulk(D0 + A_BYTES, srcB, B_BYTES, mbF + 8 * kc);
        }
    }

    const int warp_mb = (wid & 3) * 2;
    const int warp_np = (wid >> 2) * 3;

    float acc[2][6][4];
#pragma unroll
    for (int mi = 0; mi < 2; mi++)
#pragma unroll
        for (int ni = 0; ni < 6; ni++)
#pragma unroll
            for (int r = 0; r < 4; r++) acc[mi][ni][r] = 0.f;

    for (int kc = 0; kc < NCHUNK; kc++) {
        mbar_wait(mbF + 8 * kc, 0);
        const float4* As = sm4 + kc * STAGE_F4;
        const float4* Bs = As + 768;
#pragma unroll
        for (int kbl = 0; kbl < 3; kbl++) {
            float4 af4[2], bf4[3];
#pragma unroll
            for (int mi = 0; mi < 2; mi++)
                af4[mi] = As[((warp_mb + mi) * 3 + kbl) * 32 + lane];
#pragma unroll
            for (int npj = 0; npj < 3; npj++)
                bf4[npj] = Bs[((warp_np + npj) * 3 + kbl) * 32 + lane];
#pragma unroll
            for (int mi = 0; mi < 2; mi++) {
                const uint32_t* a = (const uint32_t*)&af4[mi];
#pragma unroll
                for (int npj = 0; npj < 3; npj++) {
                    const uint32_t* b = (const uint32_t*)&bf4[npj];
                    mma_tf32(acc[mi][npj * 2 + 0], a, b);
                    mma_tf32(acc[mi][npj * 2 + 1], a, b + 2);
                }
            }
        }
    }

    const int gid = lane >> 2;
    const int tig = lane & 3;
    const int pbase = warp_np * 8;
    float* outc = d_outS + (size_t)c * NP * NB;
#pragma unroll
    for (int ni = 0; ni < 6; ni++) {
        const int p = pbase + ni * 4 + tig;
        const float C1 = d_c12[p];
        const float C2 = d_c12[NP + p];
        const float* modp = d_modT + (size_t)p * NB;
        float* outp = outc + (size_t)p * NB;
#pragma unroll
        for (int mi = 0; mi < 2; mi++) {
#pragma unroll
            for (int h = 0; h < 2; h++) {
                const int b = b0 + (wid & 3) * 32 + mi * 16 + gid + h * 8;
                const float y1 = acc[mi][ni][2 * h];
                const float y2 = acc[mi][ni][2 * h + 1];
                outp[b] = y1 + C1 + modp[b] * (y2 + C2);
            }
        }
    }
}

// ---------------------------------------------------------------------------
// Kernel 2: d_outS[c][p][b] -> out[b][p][c]  (coalesced both sides)
// ---------------------------------------------------------------------------
__global__ __launch_bounds__(256) void outT_k(float* __restrict__ out) {
    __shared__ float tile[64][65];
    const int b0 = blockIdx.x * 64;
    const int p  = blockIdx.y;
    const int tid = threadIdx.x;
#pragma unroll
    for (int it = 0; it < 4; it++) {
        int i = it * 256 + tid;
        int cc = i >> 4, q = i & 15;
        float4 v = *(const float4*)(d_outS + (((size_t)cc * NP + p) * NB) + b0 + q * 4);
        tile[cc][q * 4 + 0] = v.x;
        tile[cc][q * 4 + 1] = v.y;
        tile[cc][q * 4 + 2] = v.z;
        tile[cc][q * 4 + 3] = v.w;
    }
    __syncthreads();
#pragma unroll
    for (int it = 0; it < 4; it++) {
        int i = it * 256 + tid;
        int b = i >> 4, q = i & 15;
        float4 w;
        w.x = tile[q * 4 + 0][b];
        w.y = tile[q * 4 + 1][b];
        w.z = tile[q * 4 + 2][b];
        w.w = tile[q * 4 + 3][b];
        *(float4*)(out + (size_t)(b0 + b) * (NP * CF) + (size_t)p * CF + q * 4) = w;
    }
}

// ---------------------------------------------------------------------------
extern "C" void kernel_launch(void* const* d_in, const int* in_sizes, int n_in,
                              void* d_out, int out_size) {
    const float* x        = (const float*)d_in[0];
    const float* decomp_w = (const float*)d_in[1];
    const float* trend_W  = (const float*)d_in[2];
    const float* trend_b  = (const float*)d_in[3];
    const float* seas_W   = (const float*)d_in[4];
    const float* seas_b   = (const float*)d_in[5];
    const float* lagc_W   = (const float*)d_in[6];
    const float* lagc_b   = (const float*)d_in[7];
    const float* wx       = (const float*)d_in[8];
    const float* wy       = (const float*)d_in[9];
    const float* wz       = (const float*)d_in[10];
    const float* W1       = (const float*)d_in[11];
    const float* b1       = (const float*)d_in[12];
    const float* W2       = (const float*)d_in[13];
    const float* b2       = (const float*)d_in[14];
    const float* alpha    = (const float*)d_in[15];
    float* out = (float*)d_out;

    cudaFuncSetAttribute(gemm_k, cudaFuncAttributeMaxDynamicSharedMemorySize,
                         NCHUNK * STAGE_B);

    pre_k<<<N_MOD + N_PREP + N_TR, 256>>>(x, decomp_w, trend_W, trend_b, seas_W, seas_b,
                                          lagc_W, lagc_b, wx, wy, wz,
                                          W1, b1, W2, b2, alpha);
    gemm_k<<<dim3(64, 32), 512, NCHUNK * STAGE_B>>>();
    outT_k<<<dim3(64, 96), 256>>>(out);
}

// round 13
// speedup vs baseline: 2.6513x; 1.2172x over previous
#include <cuda_runtime.h>
#include <math.h>
#include <stdint.h>

#define NB    4096
#define SEQL  168
#define CF    64
#define NP    96
#define KW    25
#define PI_F  3.14159265358979f

// chunk-contiguous fragment scratch:
// d_xA: [c][kc(7)][mb(256)][kbl(3)][128]   (m16xk8 frag blocks; one CTA stage = contiguous)
// d_MB: [c][kc(7)][np(12)][kbl(3)][128]    (n16xk8 frag blocks)
__device__ float d_xA[(size_t)CF * 7 * 256 * 3 * 128];
__device__ float d_MB[(size_t)CF * 7 * 12 * 3 * 128];
__device__ float d_modT[(size_t)NP * NB];            // [p][b]
__device__ float d_outS[(size_t)CF * NP * NB];       // [c][p][b] gemm scratch
__device__ float d_c12[2 * NP];

__device__ __forceinline__ float to_tf32(float f) {
    uint32_t u;
    asm("cvt.rna.tf32.f32 %0, %1;" : "=r"(u) : "f"(f));
    return __uint_as_float(u);
}
__device__ __forceinline__ uint32_t smem_u32(const void* p) {
    uint32_t a;
    asm("{ .reg .u64 t; cvta.to.shared.u64 t, %1; cvt.u32.u64 %0, t; }" : "=r"(a) : "l"(p));
    return a;
}
__device__ __forceinline__ void mma_tf32(float* d, const uint32_t* a, const uint32_t* b) {
    asm volatile(
        "mma.sync.aligned.m16n8k8.row.col.f32.tf32.tf32.f32 "
        "{%0,%1,%2,%3}, {%4,%5,%6,%7}, {%8,%9}, {%0,%1,%2,%3};"
        : "+f"(d[0]), "+f"(d[1]), "+f"(d[2]), "+f"(d[3])
        : "r"(a[0]), "r"(a[1]), "r"(a[2]), "r"(a[3]), "r"(b[0]), "r"(b[1]));
}
__device__ __forceinline__ void mbar_init(uint32_t a, uint32_t cnt) {
    asm volatile("mbarrier.init.shared.b64 [%0], %1;" :: "r"(a), "r"(cnt) : "memory");
}
__device__ __forceinline__ void mbar_expect_tx(uint32_t a, uint32_t bytes) {
    asm volatile("mbarrier.arrive.expect_tx.shared.b64 _, [%0], %1;"
                 :: "r"(a), "r"(bytes) : "memory");
}
__device__ __forceinline__ void mbar_wait(uint32_t a, uint32_t parity) {
    asm volatile(
        "{\n\t.reg .pred P;\n\t"
        "WL_%=:\n\t"
        "mbarrier.try_wait.parity.acquire.cta.shared::cta.b64 P, [%0], %1, 0x989680;\n\t"
        "@!P bra WL_%=;\n\t}"
        :: "r"(a), "r"(parity) : "memory");
}
__device__ __forceinline__ void mbar_arrive(uint32_t a) {
    asm volatile("mbarrier.arrive.release.cta.shared::cta.b64 _, [%0];" :: "r"(a) : "memory");
}
__device__ __forceinline__ void tma_bulk(uint32_t dst, const void* src, uint32_t bytes,
                                         uint32_t mbar) {
    asm volatile(
        "cp.async.bulk.shared::cta.global.mbarrier::complete_tx::bytes [%0], [%1], %2, [%3];"
        :: "r"(dst), "l"(src), "r"(bytes), "r"(mbar) : "memory");
}

// ---------------------------------------------------------------------------
// quantum helpers
// ---------------------------------------------------------------------------
__device__ __forceinline__ float2 cmulf(float2 a, float2 b) {
    return make_float2(a.x * b.x - a.y * b.y, a.x * b.y + a.y * b.x);
}

__device__ void run_circuit(const float qin[4], const float* __restrict__ w, float2 s[16]) {
#pragma unroll
    for (int i = 0; i < 16; i++) s[i] = make_float2(0.f, 0.f);
    s[0].x = 1.f;
#pragma unroll
    for (int l = 0; l < 3; l++) {
#pragma unroll
        for (int q = 0; q < 4; q++) {
            const int m = 8 >> q;
            float sn, cs; sincosf(0.5f * qin[q], &sn, &cs);
#pragma unroll
            for (int i = 0; i < 16; i++) {
                if ((i & m) == 0) {
                    float2 a0 = s[i], a1 = s[i | m];
                    s[i]     = make_float2(cs * a0.x - sn * a1.x, cs * a0.y - sn * a1.y);
                    s[i | m] = make_float2(sn * a0.x + cs * a1.x, sn * a0.y + cs * a1.y);
                }
            }
        }
#pragma unroll
        for (int q = 0; q < 4; q++) {
            const int m = 8 >> q;
            float phi = w[(l * 4 + q) * 3 + 0];
            float th  = w[(l * 4 + q) * 3 + 1];
            float om  = w[(l * 4 + q) * 3 + 2];
            float st, ct; sincosf(0.5f * th, &st, &ct);
            float s1, c1; sincosf(-0.5f * (phi + om), &s1, &c1);
            float s2, c2; sincosf( 0.5f * (phi - om), &s2, &c2);
            float2 U00 = make_float2( c1 * ct,  s1 * ct);
            float2 U01 = make_float2(-c2 * st, -s2 * st);
            float2 U10 = make_float2( c2 * st, -s2 * st);
            float2 U11 = make_float2( c1 * ct, -s1 * ct);
#pragma unroll
            for (int i = 0; i < 16; i++) {
                if ((i & m) == 0) {
                    float2 a0 = s[i], a1 = s[i | m];
                    float2 n0 = cmulf(U00, a0); float2 t = cmulf(U01, a1);
                    n0.x += t.x; n0.y += t.y;
                    float2 n1 = cmulf(U10, a0); t = cmulf(U11, a1);
                    n1.x += t.x; n1.y += t.y;
                    s[i] = n0; s[i | m] = n1;
                }
            }
        }
#pragma unroll
        for (int q = 0; q < 4; q++) {
            const int cm = 8 >> q;
            const int tm = 8 >> ((q + 1) & 3);
#pragma unroll
            for (int i = 0; i < 16; i++) {
                if ((i & cm) && !(i & tm)) {
                    float2 t = s[i]; s[i] = s[i | tm]; s[i | tm] = t;
                }
            }
        }
    }
}

__device__ __forceinline__ void expvals(const float2 s[16], int pauli, float* o) {
#pragma unroll
    for (int q = 0; q < 4; q++) {
        const int m = 8 >> q;
        float acc = 0.f;
#pragma unroll
        for (int i = 0; i < 16; i++) {
            if ((i & m) == 0) {
                float2 a0 = s[i], a1 = s[i | m];
                if (pauli == 0)      acc += a0.x * a1.x + a0.y * a1.y;
                else if (pauli == 1) acc += a0.x * a1.y - a0.y * a1.x;
                else                 acc += a0.x * a0.x + a0.y * a0.y
                                          - a1.x * a1.x - a1.y * a1.y;
            }
        }
        o[q] = (pauli == 2) ? acc : 2.f * acc;
    }
}

// ---------------------------------------------------------------------------
// Kernel 0 (fused pre-work): heterogeneous blocks.
//   [0, 128)        : mod   (96 active threads)   -> d_modT
//   [128, 3200)     : transpose x2 sub-tiles      -> d_xA
//   [3200, 3712)    : prep (c, p-octet), softmax shared across 12 p -> d_MB, d_c12
// ---------------------------------------------------------------------------
#define N_MODB   128
#define N_TRB    3072
#define N_PREPB  512

__global__ __launch_bounds__(256, 4) void pre_k(const float* __restrict__ x,
                      const float* __restrict__ decomp_w,
                      const float* __restrict__ trend_W, const float* __restrict__ trend_b,
                      const float* __restrict__ seas_W,  const float* __restrict__ seas_b,
                      const float* __restrict__ lagc_W,  const float* __restrict__ lagc_b,
                      const float* __restrict__ wx, const float* __restrict__ wy,
                      const float* __restrict__ wz,
                      const float* __restrict__ W1, const float* __restrict__ b1,
                      const float* __restrict__ W2, const float* __restrict__ b2,
                      const float* __restrict__ alpha) {
    __shared__ float sh_raw[8 * 32 * 33];      // 33.8KB
    const int bid = blockIdx.x;
    const int tid = threadIdx.x;

    if (bid < N_MODB) {
        // ================= mod path =================
        float (*feats_s)[13] = (float (*)[13])sh_raw;
        const int bl = tid & 31;
        const int r  = tid >> 5;
        const bool act = tid < 96;
        const int b  = bid * 32 + bl;
        float h[12];
        if (act) {
            const int lags[11] = {167, 166, 165, 164, 163, 162, 145, 144, 143, 1, 0};
            float lag[11];
#pragma unroll
            for (int j = 0; j < 11; j++)
                lag[j] = x[(size_t)b * (SEQL * CF) + lags[j] * CF + (CF - 1)];
            float qin[4];
#pragma unroll
            for (int q = 0; q < 4; q++) {
                float s = lagc_b[q];
#pragma unroll
                for (int j = 0; j < 11; j++) s += lag[j] * lagc_W[q * 11 + j];
                qin[q] = tanhf(s) * PI_F;
            }
            const float* w = (r == 0) ? wx : (r == 1) ? wy : wz;
            float2 st[16];
            float f4[4];
            run_circuit(qin, w, st);
            expvals(st, r, f4);
#pragma unroll
            for (int q = 0; q < 4; q++) feats_s[bl][r * 4 + q] = f4[q];
        }
        __syncthreads();
        if (act) {
            float feats[12];
#pragma unroll
            for (int j = 0; j < 12; j++) feats[j] = feats_s[bl][j];
#pragma unroll
            for (int i = 0; i < 12; i++) {
                float s = b1[i];
#pragma unroll
                for (int j = 0; j < 12; j++) s += feats[j] * W1[i * 12 + j];
                h[i] = fmaxf(s, 0.f);
            }
            for (int pp = 0; pp < 32; pp++) {
                int p = r * 32 + pp;
                float s = b2[p];
#pragma unroll
                for (int i = 0; i < 12; i++) s += h[i] * W2[p * 12 + i];
                d_modT[(size_t)p * NB + b] = tanhf(s);
            }
        }
    } else if (bid < N_MODB + N_TRB) {
        // ================= transpose path (2 sub-tiles) =================
        float (*sh)[32][33] = (float (*)[32][33])sh_raw;
        const int t  = bid - N_MODB;
        const int c0 = (t & 7) * 8;
        const int l0 = ((t >> 3) % 6) * 32;
        const int bbase = (t / 48) * 64;
        const float4* x4 = (const float4*)x;
        float4* o4 = (float4*)d_xA;
        for (int sub = 0; sub < 2; sub++) {
            const int b0 = bbase + sub * 32;
#pragma unroll
            for (int it = 0; it < 8; it++) {
                int i = it * 256 + tid;
                int c4i = i & 1, l = (i >> 1) & 31, b = i >> 6;
                int lg = l0 + l;
                float4 v = make_float4(0.f, 0.f, 0.f, 0.f);
                if (lg < SEQL)
                    v = x4[(size_t)(b0 + b) * (SEQL * 16) + (size_t)lg * 16 + (c0 >> 2) + c4i];
                sh[c4i * 4 + 0][l][b] = to_tf32(v.x);
                sh[c4i * 4 + 1][l][b] = to_tf32(v.y);
                sh[c4i * 4 + 2][l][b] = to_tf32(v.z);
                sh[c4i * 4 + 3][l][b] = to_tf32(v.w);
            }
            __syncthreads();
#pragma unroll
            for (int it = 0; it < 8; it++) {
                int i = it * 256 + tid;
                int lane = i & 31, kbl = (i >> 5) & 3, mbl = (i >> 7) & 1, cl = i >> 8;
                int kb_g = (l0 >> 3) + kbl;
                if (kb_g >= 21) continue;
                int kc = kb_g / 3, kr = kb_g - kc * 3;
                int g = lane >> 2, tg = lane & 3;
                float4 w;
                w.x = sh[cl][kbl * 8 + tg]    [mbl * 16 + g];
                w.y = sh[cl][kbl * 8 + tg]    [mbl * 16 + g + 8];
                w.z = sh[cl][kbl * 8 + tg + 4][mbl * 16 + g];
                w.w = sh[cl][kbl * 8 + tg + 4][mbl * 16 + g + 8];
                size_t idx4 = ((((size_t)(c0 + cl) * 7 + kc) * 256 + (b0 >> 4) + mbl) * 3 + kr)
                            * 32 + lane;
                o4[idx4] = w;
            }
            __syncthreads();
        }
    } else {
        // ================= prep path: (c, p-octet) =================
        const int q0 = bid - (N_MODB + N_TRB);
        const int c  = q0 >> 3;
        const int pg = q0 & 7;
        const int j  = tid;
        float* ker = sh_raw;
        float* a_sh = sh_raw + KW;
        if (j == 0) {
            float mx = -1e30f;
            for (int k = 0; k < KW; k++) mx = fmaxf(mx, decomp_w[c * KW + k]);
            float sum = 0.f, e[KW];
            for (int k = 0; k < KW; k++) { e[k] = expf(decomp_w[c * KW + k] - mx); sum += e[k]; }
            for (int k = 0; k < KW; k++) ker[k] = e[k] / sum;
            a_sh[0] = 1.f / (1.f + expf(-alpha[0]));
        }
        __syncthreads();
        if (j < SEQL) {
            const float a = a_sh[0];
            const int kb = j >> 3, kk = j & 7, t = kk & 3, th = kk >> 2;
            const int kc = kb / 3, kr = kb - kc * 3;
            for (int pi = 0; pi < 12; pi++) {
                const int p = pg * 12 + pi;
                const float* sW = seas_W + p * SEQL;
                const float* tW = trend_W + p * SEQL;
                float sA = 0.f, sB = 0.f;
                if (j == 0) {
                    for (int k = 0; k <= 12; k++) {
                        float wk = ker[k];
                        for (int l = 0; l <= 12 - k; l++) { sA += wk * sW[l]; sB += wk * tW[l]; }
                    }
                } else if (j == SEQL - 1) {
                    for (int k = 12; k < KW; k++) {
                        float wk = ker[k];
                        for (int l = 179 - k; l < SEQL; l++) { sA += wk * sW[l]; sB += wk * tW[l]; }
                    }
                } else {
                    for (int k = 0; k < KW; k++) {
                        int l = j + 12 - k;
                        if (l >= 0 && l < SEQL) { float wk = ker[k]; sA += wk * sW[l]; sB += wk * tW[l]; }
                    }
                }
                float A = sW[j] - sA;
                float M1 = to_tf32(a * A + (1.f - a) * sB);   // n = 2p
                float M2 = to_tf32(a * A);                    // n = 2p+1
#pragma unroll
                for (int h2 = 0; h2 < 2; h2++) {
                    int n = 2 * p + h2;
                    int np = n >> 4, nn = n & 15, qq = nn >> 3, g = nn & 7;
                    int lane = g * 4 + t, reg = 2 * qq + th;
                    d_MB[((((size_t)c * 7 + kc) * 12 + np) * 3 + kr) * 128 + lane * 4 + reg]
                        = h2 ? M2 : M1;
                }
                if (c == 0 && j == 0) {
                    d_c12[p]      = a * seas_b[p] + (1.f - a) * trend_b[p];
                    d_c12[NP + p] = a * seas_b[p];
                }
            }
        }
    }
}

// ---------------------------------------------------------------------------
// Kernel 1: persistent TF32 mma.sync GEMM; continuous 7-stage TMA ring.
// 544 threads: warps 0-15 consumers (4m x 4n, warp tile m32 x n48),
// warp 16 producer. Tile = (c, 128 batches); NTILES = 2048.
// ---------------------------------------------------------------------------
#define STAGE_F4   1920                  // A 768 + B 1152 float4
#define STAGE_B    (STAGE_F4 * 16)       // 30720 bytes
#define A_BYTES    12288
#define B_BYTES    18432
#define NCHUNK     7
#define NTILES     2048

__global__ __launch_bounds__(544, 1) void gemm_k() {
    extern __shared__ __align__(16) float4 sm4[];
    __shared__ __align__(8) uint64_t mbar[2 * NCHUNK];  // full[7], empty[7]

    const int tid = threadIdx.x;
    const int wid  = tid >> 5;
    const int lane = tid & 31;
    const int bid = blockIdx.x;
    const int stride = gridDim.x;

    const uint32_t smb = smem_u32(sm4);
    const uint32_t mbF = smem_u32(&mbar[0]);
    const uint32_t mbE = smem_u32(&mbar[NCHUNK]);

    if (tid == 0) {
#pragma unroll
        for (int s = 0; s < NCHUNK; s++) {
            mbar_init(mbF + 8 * s, 1);   // expect_tx arrival + tx bytes
            mbar_init(mbE + 8 * s, 16);  // one arrive per consumer warp
        }
    }
    __syncthreads();

    if (wid == 16) {
        // ---- producer warp: keep the ring one tile ahead ----
        int it = 0;
        for (int t = bid; t < NTILES; t += stride) {
            const int c   = t >> 5;
            const int mb0 = (t & 31) * 8;
#pragma unroll
            for (int kc = 0; kc < NCHUNK; kc++) {
                if (it > 0) mbar_wait(mbE + 8 * kc, (it - 1) & 1);
                if (lane == 0) {
                    const uint32_t D0 = smb + kc * STAGE_B;
                    const float* srcA = d_xA + (((size_t)c * 7 + kc) * 256 + mb0) * 384;
                    const float* srcB = d_MB + (((size_t)c * 7 + kc) * 12) * 384;
                    mbar_expect_tx(mbF + 8 * kc, STAGE_B);
                    tma_bulk(D0, srcA, A_BYTES, mbF + 8 * kc);
                    tma_bulk(D0 + A_BYTES, srcB, B_BYTES, mbF + 8 * kc);
                }
            }
            it++;
        }
    } else {
        // ---- consumer warps 0..15 : 4m x 4n ----
        const int warp_mb = (wid & 3) * 2;
        const int warp_np = (wid >> 2) * 3;
        const int gid = lane >> 2;
        const int tig = lane & 3;
        int it = 0;

        for (int t = bid; t < NTILES; t += stride) {
            const int c  = t >> 5;
            const int b0 = (t & 31) * 128;

            float acc[2][6][4];
#pragma unroll
            for (int mi = 0; mi < 2; mi++)
#pragma unroll
                for (int ni = 0; ni < 6; ni++)
#pragma unroll
                    for (int r = 0; r < 4; r++) acc[mi][ni][r] = 0.f;

#pragma unroll 1
            for (int kc = 0; kc < NCHUNK; kc++) {
                mbar_wait(mbF + 8 * kc, it & 1);
                const float4* As = sm4 + kc * STAGE_F4;
                const float4* Bs = As + 768;
#pragma unroll
                for (int kbl = 0; kbl < 3; kbl++) {
                    float4 af4[2], bf4[3];
#pragma unroll
                    for (int mi = 0; mi < 2; mi++)
                        af4[mi] = As[((warp_mb + mi) * 3 + kbl) * 32 + lane];
#pragma unroll
                    for (int npj = 0; npj < 3; npj++)
                        bf4[npj] = Bs[((warp_np + npj) * 3 + kbl) * 32 + lane];
#pragma unroll
                    for (int mi = 0; mi < 2; mi++) {
                        const uint32_t* a = (const uint32_t*)&af4[mi];
#pragma unroll
                        for (int npj = 0; npj < 3; npj++) {
                            const uint32_t* b = (const uint32_t*)&bf4[npj];
                            mma_tf32(acc[mi][npj * 2 + 0], a, b);
                            mma_tf32(acc[mi][npj * 2 + 1], a, b + 2);
                        }
                    }
                }
                if (lane == 0) mbar_arrive(mbE + 8 * kc);
            }

            // epilogue -> d_outS[c][p][b]
            const int pbase = warp_np * 8;
            float* outc = d_outS + (size_t)c * NP * NB;
#pragma unroll
            for (int ni = 0; ni < 6; ni++) {
                const int p = pbase + ni * 4 + tig;
                const float C1 = d_c12[p];
                const float C2 = d_c12[NP + p];
                const float* modp = d_modT + (size_t)p * NB;
                float* outp = outc + (size_t)p * NB;
#pragma unroll
                for (int mi = 0; mi < 2; mi++) {
#pragma unroll
                    for (int h = 0; h < 2; h++) {
                        const int b = b0 + (wid & 3) * 32 + mi * 16 + gid + h * 8;
                        const float y1 = acc[mi][ni][2 * h];
                        const float y2 = acc[mi][ni][2 * h + 1];
                        outp[b] = y1 + C1 + modp[b] * (y2 + C2);
                    }
                }
            }
            it++;
        }
    }
}

// ---------------------------------------------------------------------------
// Kernel 2: d_outS[c][p][b] -> out[b][p][c]  (coalesced both sides)
// ---------------------------------------------------------------------------
__global__ __launch_bounds__(256) void outT_k(float* __restrict__ out) {
    __shared__ float tile[64][65];
    const int b0 = blockIdx.x * 64;
    const int p  = blockIdx.y;
    const int tid = threadIdx.x;
#pragma unroll
    for (int it = 0; it < 4; it++) {
        int i = it * 256 + tid;
        int cc = i >> 4, q = i & 15;
        float4 v = *(const float4*)(d_outS + (((size_t)cc * NP + p) * NB) + b0 + q * 4);
        tile[cc][q * 4 + 0] = v.x;
        tile[cc][q * 4 + 1] = v.y;
        tile[cc][q * 4 + 2] = v.z;
        tile[cc][q * 4 + 3] = v.w;
    }
    __syncthreads();
#pragma unroll
    for (int it = 0; it < 4; it++) {
        int i = it * 256 + tid;
        int b = i >> 4, q = i & 15;
        float4 w;
        w.x = tile[q * 4 + 0][b];
        w.y = tile[q * 4 + 1][b];
        w.z = tile[q * 4 + 2][b];
        w.w = tile[q * 4 + 3][b];
        *(float4*)(out + (size_t)(b0 + b) * (NP * CF) + (size_t)p * CF + q * 4) = w;
    }
}

// ---------------------------------------------------------------------------
extern "C" void kernel_launch(void* const* d_in, const int* in_sizes, int n_in,
                              void* d_out, int out_size) {
    const float* x        = (const float*)d_in[0];
    const float* decomp_w = (const float*)d_in[1];
    const float* trend_W  = (const float*)d_in[2];
    const float* trend_b  = (const float*)d_in[3];
    const float* seas_W   = (const float*)d_in[4];
    const float* seas_b   = (const float*)d_in[5];
    const float* lagc_W   = (const float*)d_in[6];
    const float* lagc_b   = (const float*)d_in[7];
    const float* wx       = (const float*)d_in[8];
    const float* wy       = (const float*)d_in[9];
    const float* wz       = (const float*)d_in[10];
    const float* W1       = (const float*)d_in[11];
    const float* b1       = (const float*)d_in[12];
    const float* W2       = (const float*)d_in[13];
    const float* b2       = (const float*)d_in[14];
    const float* alpha    = (const float*)d_in[15];
    float* out = (float*)d_out;

    static int n_sm = 0;
    if (n_sm == 0) {
        cudaDeviceGetAttribute(&n_sm, cudaDevAttrMultiProcessorCount, 0);
        if (n_sm <= 0) n_sm = 148;
        cudaFuncSetAttribute(gemm_k, cudaFuncAttributeMaxDynamicSharedMemorySize,
                             NCHUNK * STAGE_B);
    }

    pre_k<<<N_MODB + N_TRB + N_PREPB, 256>>>(x, decomp_w, trend_W, trend_b, seas_W, seas_b,
                                             lagc_W, lagc_b, wx, wy, wz,
                                             W1, b1, W2, b2, alpha);
    gemm_k<<<n_sm, 544, NCHUNK * STAGE_B>>>();
    outT_k<<<dim3(64, 96), 256>>>(out);
}